// round 4
// baseline (speedup 1.0000x reference)
#include <cuda_runtime.h>
#include <cuda_bf16.h>
#include <cstdint>
#include <math.h>

#define B_SZ   4
#define C_DIM  512
#define N_DIM  512
#define S_DIM  64
#define L_DIM  8192
#define HALF_L 4096

typedef __nv_bfloat16 bf16;
typedef unsigned long long ull;

// ---------------------------------------------------------------------------
// Scratch (allocation-free rule: __device__ globals)
// ---------------------------------------------------------------------------
__device__ __align__(128) float g_x  [(size_t)B_SZ * N_DIM * L_DIM];   // gemm1 out (fp32)
__device__ __align__(128) bf16  g_inh[(size_t)B_SZ * C_DIM * L_DIM];
__device__ __align__(128) bf16  g_inl[(size_t)B_SZ * C_DIM * L_DIM];
__device__ __align__(128) bf16  g_yh [(size_t)B_SZ * N_DIM * L_DIM];
__device__ __align__(128) bf16  g_yl [(size_t)B_SZ * N_DIM * L_DIM];
__device__ __align__(128) bf16  g_bh [C_DIM * N_DIM];
__device__ __align__(128) bf16  g_bl [C_DIM * N_DIM];
__device__ __align__(128) bf16  g_ch [C_DIM * N_DIM];
__device__ __align__(128) bf16  g_cl [C_DIM * N_DIM];
__device__ __align__(128) ull   g_st [(size_t)B_SZ * N_DIM * 32 * 2];  // mid-point states (hr2, hi2)

// ---------------------------------------------------------------------------
// Helpers (base PTX only: compute_103 virtual arch — no 'a'-gated features)
// ---------------------------------------------------------------------------
__device__ __forceinline__ uint32_t smem_u32(const void* p) {
    uint32_t a;
    asm("{ .reg .u64 t; cvta.to.shared.u64 t, %1; cvt.u32.u64 %0, t; }" : "=r"(a) : "l"(p));
    return a;
}
__device__ __forceinline__ void cpa16(uint32_t d, const void* s) {
    asm volatile("cp.async.cg.shared.global [%0], [%1], 16;" :: "r"(d), "l"(s));
}
#define CP_COMMIT() asm volatile("cp.async.commit_group;" ::: "memory")
#define CP_WAIT2()  asm volatile("cp.async.wait_group 2;"  ::: "memory")

#define LDSM_X4(r0,r1,r2,r3,addr) \
    asm volatile("ldmatrix.sync.aligned.m8n8.x4.shared.b16 {%0,%1,%2,%3}, [%4];" \
        : "=r"(r0), "=r"(r1), "=r"(r2), "=r"(r3) : "r"(addr))
#define LDSM_X4T(r0,r1,r2,r3,addr) \
    asm volatile("ldmatrix.sync.aligned.m8n8.x4.trans.shared.b16 {%0,%1,%2,%3}, [%4];" \
        : "=r"(r0), "=r"(r1), "=r"(r2), "=r"(r3) : "r"(addr))

#define MMA16816(d, a, b0v, b1v) \
    asm volatile("mma.sync.aligned.m16n8k16.row.col.f32.bf16.bf16.f32 " \
        "{%0,%1,%2,%3}, {%4,%5,%6,%7}, {%8,%9}, {%0,%1,%2,%3};" \
        : "+f"((d)[0]), "+f"((d)[1]), "+f"((d)[2]), "+f"((d)[3]) \
        : "r"((a)[0]), "r"((a)[1]), "r"((a)[2]), "r"((a)[3]), "r"(b0v), "r"(b1v))

// packed f32x2 (PTX ISA 8.6, base sm_100+ — not an 'a' feature)
__device__ __forceinline__ ull pk(float lo, float hi) {
    ull r; asm("mov.b64 %0, {%1,%2};" : "=l"(r) : "f"(lo), "f"(hi)); return r;
}
__device__ __forceinline__ void upk(ull v, float& lo, float& hi) {
    asm("mov.b64 {%0,%1}, %2;" : "=f"(lo), "=f"(hi) : "l"(v));
}
__device__ __forceinline__ ull f2fma(ull a, ull b, ull c) {
    ull d; asm("fma.rn.f32x2 %0, %1, %2, %3;" : "=l"(d) : "l"(a), "l"(b), "l"(c)); return d;
}
__device__ __forceinline__ ull f2mul(ull a, ull b) {
    ull d; asm("mul.rn.f32x2 %0, %1, %2;" : "=l"(d) : "l"(a), "l"(b)); return d;
}
__device__ __forceinline__ ull f2add(ull a, ull b) {
    ull d; asm("add.rn.f32x2 %0, %1, %2;" : "=l"(d) : "l"(a), "l"(b)); return d;
}

// ---------------------------------------------------------------------------
// fp32 -> bf16 hi/lo split (pre-pass)
// ---------------------------------------------------------------------------
__global__ __launch_bounds__(256) void split_fp32(
    const float* __restrict__ src, bf16* __restrict__ hi, bf16* __restrict__ lo, int n)
{
    int i = (blockIdx.x * 256 + threadIdx.x) * 4;
    if (i >= n) return;
    float4 v = *(const float4*)(src + i);
    bf16 h0 = __float2bfloat16_rn(v.x), h1 = __float2bfloat16_rn(v.y);
    bf16 h2 = __float2bfloat16_rn(v.z), h3 = __float2bfloat16_rn(v.w);
    bf16 l0 = __float2bfloat16_rn(v.x - __bfloat162float(h0));
    bf16 l1 = __float2bfloat16_rn(v.y - __bfloat162float(h1));
    bf16 l2 = __float2bfloat16_rn(v.z - __bfloat162float(h2));
    bf16 l3 = __float2bfloat16_rn(v.w - __bfloat162float(h3));
    ((__nv_bfloat162*)(hi + i))[0] = __nv_bfloat162(h0, h1);
    ((__nv_bfloat162*)(hi + i))[1] = __nv_bfloat162(h2, h3);
    ((__nv_bfloat162*)(lo + i))[0] = __nv_bfloat162(l0, l1);
    ((__nv_bfloat162*)(lo + i))[1] = __nv_bfloat162(l2, l3);
}

// ---------------------------------------------------------------------------
// HMMA GEMM (unchanged from R3): Out[b] = W(512x512) @ X[b](512x8192)
// ---------------------------------------------------------------------------
#define STAGE  18432
#define A_BYTES 10240
#define NCHUNK 48
#define GEMM_SMEM (4 * STAGE)

__global__ __launch_bounds__(256, 2) void hgemm(
    const bf16* __restrict__ Ah, const bf16* __restrict__ Al,
    const bf16* __restrict__ Bh0, const bf16* __restrict__ Bl0,
    float* __restrict__ Out)
{
    extern __shared__ char smem[];
    const uint32_t sb = smem_u32(smem);
    const int tid  = threadIdx.x;
    const int lane = tid & 31, wid = tid >> 5;
    const int n0 = blockIdx.x * 128;
    const int m0 = blockIdx.y * 128;
    const bf16* Bh = Bh0 + (size_t)blockIdx.z * C_DIM * L_DIM;
    const bf16* Bl = Bl0 + (size_t)blockIdx.z * C_DIM * L_DIM;
    float* Ob = Out + (size_t)blockIdx.z * N_DIM * L_DIM;

    const int am = tid >> 2, ac = tid & 3;
    const int bk = tid >> 4, bc = tid & 15;

    auto load_stage = [&](int cl, int st) {
        if (cl < NCHUNK) {
            const bf16* As = (cl < 32) ? Ah : Al;
            const bf16* Bs = (cl >= 16 && cl < 32) ? Bl : Bh;
            const int k0 = (cl & 15) << 5;
            const uint32_t s0 = sb + (uint32_t)st * STAGE;
            cpa16(s0 + am * 80 + ac * 16,
                  As + (size_t)(m0 + am) * C_DIM + k0 + ac * 8);
            cpa16(s0 + (am + 64) * 80 + ac * 16,
                  As + (size_t)(m0 + am + 64) * C_DIM + k0 + ac * 8);
            {
                int c1 = (bc & 8) | ((bc ^ (bk & 7)) & 7);
                cpa16(s0 + A_BYTES + bk * 256 + c1 * 16,
                      Bs + (size_t)(k0 + bk) * L_DIM + n0 + bc * 8);
                int k2 = bk + 16;
                int c2 = (bc & 8) | ((bc ^ (k2 & 7)) & 7);
                cpa16(s0 + A_BYTES + k2 * 256 + c2 * 16,
                      Bs + (size_t)(k0 + k2) * L_DIM + n0 + bc * 8);
            }
        }
        CP_COMMIT();
    };

    const int wm = (wid >> 2) * 64;
    const int wn = (wid & 3) * 32;
    const uint32_t a_base = (uint32_t)(wm + (lane & 15)) * 80 + ((lane >> 4) * 16);
    uint32_t b_off[2];
#pragma unroll
    for (int nt = 0; nt < 2; nt++) {
        int g  = (wn >> 3) + nt * 2 + (lane >> 4);
        int gp = (g & 8) | ((g ^ (lane & 7)) & 7);
        b_off[nt] = (uint32_t)(lane & 15) * 256 + gp * 16;
    }

    float acc[4][4][4];
#pragma unroll
    for (int mt = 0; mt < 4; mt++)
#pragma unroll
        for (int j = 0; j < 4; j++)
#pragma unroll
            for (int r = 0; r < 4; r++) acc[mt][j][r] = 0.f;

    load_stage(0, 0); load_stage(1, 1); load_stage(2, 2);

    for (int c = 0; c < NCHUNK; c++) {
        CP_WAIT2();
        __syncthreads();
        load_stage(c + 3, (c + 3) & 3);

        const uint32_t Abase = sb + (uint32_t)(c & 3) * STAGE;
        const uint32_t Bbase = Abase + A_BYTES;
#pragma unroll
        for (int kh = 0; kh < 2; kh++) {
            uint32_t a[4][4], b[2][4];
#pragma unroll
            for (int mt = 0; mt < 4; mt++)
                LDSM_X4(a[mt][0], a[mt][1], a[mt][2], a[mt][3],
                        Abase + a_base + mt * (16 * 80) + kh * 32);
#pragma unroll
            for (int nt = 0; nt < 2; nt++)
                LDSM_X4T(b[nt][0], b[nt][1], b[nt][2], b[nt][3],
                         Bbase + b_off[nt] + kh * 4096);
#pragma unroll
            for (int mt = 0; mt < 4; mt++) {
                MMA16816(acc[mt][0], a[mt], b[0][0], b[0][1]);
                MMA16816(acc[mt][1], a[mt], b[0][2], b[0][3]);
                MMA16816(acc[mt][2], a[mt], b[1][0], b[1][1]);
                MMA16816(acc[mt][3], a[mt], b[1][2], b[1][3]);
            }
        }
    }

    const int er = lane >> 2, ec = (lane & 3) * 2;
#pragma unroll
    for (int mt = 0; mt < 4; mt++) {
#pragma unroll
        for (int j = 0; j < 4; j++) {
            size_t base = (size_t)(m0 + wm + mt * 16 + er) * L_DIM + (n0 + wn + j * 8 + ec);
            *(float2*)&Ob[base]             = make_float2(acc[mt][j][0], acc[mt][j][1]);
            *(float2*)&Ob[base + 8 * L_DIM] = make_float2(acc[mt][j][2], acc[mt][j][3]);
        }
    }
}

// ---------------------------------------------------------------------------
// Scan phase A: lean scan of l in [0, 4096) for every chain; store final
// packed state (hr2, hi2) per (chain, lane). No y output. f32x2 throughout.
// ---------------------------------------------------------------------------
__global__ __launch_bounds__(128) void scan_phaseA(
    const float* __restrict__ X, ull* __restrict__ St,
    const float* __restrict__ Ar, const float* __restrict__ Ai)
{
    const int lane = threadIdx.x;
    const int w = threadIdx.y;
    const int chain = blockIdx.x * 4 + w;     // b*512 + n
    const int n = chain & (N_DIM - 1);

    __shared__ ull xs2[4][32];

    const int s0 = n * S_DIM + lane * 2;
    float2 av = *(const float2*)&Ar[s0];
    float2 wv = *(const float2*)&Ai[s0];
    const float er0 = expf(av.x), er1 = expf(av.y);
    const float li0 = er0 * sinf(wv.x), li1 = er1 * sinf(wv.y);
    const ull lr2  = pk(er0 * cosf(wv.x), er1 * cosf(wv.y));
    const ull li2  = pk(li0, li1);
    const ull mli2 = pk(-li0, -li1);

    ull hr = 0ull, hic = 0ull;
    const float* xp = X + (size_t)chain * L_DIM;

    for (int l0 = 0; l0 < HALF_L; l0 += 32) {
        float xv = xp[l0 + lane];
        xs2[w][lane] = pk(xv, xv);
        __syncwarp();
#pragma unroll
        for (int t = 0; t < 32; t++) {
            ull x2 = xs2[w][t];
            ull t1 = f2fma(mli2, hic, x2);
            ull t2 = f2mul(li2, hr);
            hr  = f2fma(lr2, hr, t1);
            hic = f2fma(lr2, hic, t2);
        }
        __syncwarp();
    }
    St[(size_t)chain * 64 + lane * 2]     = hr;
    St[(size_t)chain * 64 + lane * 2 + 1] = hic;
}

// ---------------------------------------------------------------------------
// Scan phase B: full scan with projection/output. 2 warps per chain, one per
// 4096-step half; half 1 seeds from phase-A state. Emits bf16 hi/lo y.
// ---------------------------------------------------------------------------
__global__ __launch_bounds__(128) void scan_phaseB(
    const float* __restrict__ X,
    bf16* __restrict__ Yh, bf16* __restrict__ Yl,
    const ull* __restrict__ St,
    const float* __restrict__ Ar, const float* __restrict__ Ai,
    const float* __restrict__ Ew)
{
    const int lane = threadIdx.x;
    const int w = threadIdx.y;
    const int wg = blockIdx.x * 4 + w;
    const int chain = wg >> 1;
    const int half  = wg & 1;
    const int n = chain & (N_DIM - 1);

    __shared__ ull xs2[4][32];
    __shared__ ull part[4][32][33];   // [warp][step][mode-lane], pad 33 -> conflict-free

    const int s0 = n * S_DIM + lane * 2;
    float2 av = *(const float2*)&Ar[s0];
    float2 wv = *(const float2*)&Ai[s0];
    float2 ev = *(const float2*)&Ew[s0];
    const float er0 = expf(av.x), er1 = expf(av.y);
    const float li0 = er0 * sinf(wv.x), li1 = er1 * sinf(wv.y);
    const ull lr2  = pk(er0 * cosf(wv.x), er1 * cosf(wv.y));
    const ull li2  = pk(li0, li1);
    const ull mli2 = pk(-li0, -li1);
    const ull e2   = pk(ev.x, ev.y);

    ull hr = 0ull, hic = 0ull;
    if (half) {
        hr  = St[(size_t)chain * 64 + lane * 2];
        hic = St[(size_t)chain * 64 + lane * 2 + 1];
    }

    const int base = half * HALF_L;
    const float* xp = X + (size_t)chain * L_DIM + base;
    bf16* yhp = Yh + (size_t)chain * L_DIM + base;
    bf16* ylp = Yl + (size_t)chain * L_DIM + base;

    for (int l0 = 0; l0 < HALF_L; l0 += 32) {
        float xv = xp[l0 + lane];
        xs2[w][lane] = pk(xv, xv);
        __syncwarp();
#pragma unroll
        for (int t = 0; t < 32; t++) {
            ull x2 = xs2[w][t];
            ull t1 = f2fma(mli2, hic, x2);
            ull t2 = f2mul(li2, hr);
            hr  = f2fma(lr2, hr, t1);
            hic = f2fma(lr2, hic, t2);
            part[w][t][lane] = f2mul(e2, hr);
        }
        __syncwarp();
        // thread `lane` reduces time-step t=lane over 32 packed lanes (64 modes)
        const ull* pr = &part[w][lane][0];
        ull acc2 = f2add(pr[0], pr[1]);
#pragma unroll
        for (int q = 2; q < 32; q += 2)
            acc2 = f2add(acc2, f2add(pr[q], pr[q + 1]));
        float aa, ab; upk(acc2, aa, ab);
        float acc = aa + ab;
        bf16 h = __float2bfloat16_rn(acc);
        yhp[l0 + lane] = h;
        ylp[l0 + lane] = __float2bfloat16_rn(acc - __bfloat162float(h));
        __syncwarp();
    }
}

// ---------------------------------------------------------------------------
extern "C" void kernel_launch(void* const* d_in, const int* in_sizes, int n_in,
                              void* d_out, int out_size)
{
    const float* inp = (const float*)d_in[0];  // [B, C, L]
    const float* ar  = (const float*)d_in[1];  // [N, S]
    const float* ai  = (const float*)d_in[2];  // [N, S]
    const float* Bm  = (const float*)d_in[3];  // [N, C]
    const float* Cm  = (const float*)d_in[4];  // [C, N]
    const float* E   = (const float*)d_in[5];  // [N, S]
    float* out = (float*)d_out;                // [B, C, L]

    float *xp;  bf16 *inh, *inl, *yh, *yl, *bh, *bl, *ch, *cl;  ull* st;
    cudaGetSymbolAddress((void**)&xp,  g_x);
    cudaGetSymbolAddress((void**)&inh, g_inh);
    cudaGetSymbolAddress((void**)&inl, g_inl);
    cudaGetSymbolAddress((void**)&yh,  g_yh);
    cudaGetSymbolAddress((void**)&yl,  g_yl);
    cudaGetSymbolAddress((void**)&bh,  g_bh);
    cudaGetSymbolAddress((void**)&bl,  g_bl);
    cudaGetSymbolAddress((void**)&ch,  g_ch);
    cudaGetSymbolAddress((void**)&cl,  g_cl);
    cudaGetSymbolAddress((void**)&st,  g_st);

    cudaFuncSetAttribute(hgemm, cudaFuncAttributeMaxDynamicSharedMemorySize, GEMM_SMEM);

    const int n_in_elems = B_SZ * C_DIM * L_DIM;
    const int n_w = C_DIM * N_DIM;

    split_fp32<<<n_in_elems / 1024, 256>>>(inp, inh, inl, n_in_elems);
    split_fp32<<<n_w / 1024, 256>>>(Bm, bh, bl, n_w);
    split_fp32<<<n_w / 1024, 256>>>(Cm, ch, cl, n_w);

    dim3 gg(L_DIM / 128, N_DIM / 128, B_SZ);
    hgemm<<<gg, 256, GEMM_SMEM>>>(bh, bl, inh, inl, xp);              // x = B @ input
    scan_phaseA<<<(B_SZ * N_DIM) / 4, dim3(32, 4)>>>(xp, st, ar, ai);
    scan_phaseB<<<(B_SZ * N_DIM) / 2, dim3(32, 4)>>>(xp, yh, yl, st, ar, ai, E);
    hgemm<<<gg, 256, GEMM_SMEM>>>(ch, cl, yh, yl, out);               // out = C @ y
}

// round 5
// speedup vs baseline: 1.1641x; 1.1641x over previous
#include <cuda_runtime.h>
#include <cuda_bf16.h>
#include <cstdint>
#include <math.h>

#define B_SZ   4
#define C_DIM  512
#define N_DIM  512
#define S_DIM  64
#define L_DIM  8192
#define SEG    2048
#define HALF_L 4096

typedef __nv_bfloat16 bf16;

// ---------------------------------------------------------------------------
// Scratch (allocation-free rule: __device__ globals)
// ---------------------------------------------------------------------------
__device__ __align__(128) float g_x  [(size_t)B_SZ * N_DIM * L_DIM];   // gemm1 out (fp32)
__device__ __align__(128) bf16  g_inh[(size_t)B_SZ * C_DIM * L_DIM];
__device__ __align__(128) bf16  g_inl[(size_t)B_SZ * C_DIM * L_DIM];
__device__ __align__(128) bf16  g_yh [(size_t)B_SZ * N_DIM * L_DIM];
__device__ __align__(128) bf16  g_yl [(size_t)B_SZ * N_DIM * L_DIM];
__device__ __align__(128) bf16  g_bh [C_DIM * N_DIM];
__device__ __align__(128) bf16  g_bl [C_DIM * N_DIM];
__device__ __align__(128) bf16  g_ch [C_DIM * N_DIM];
__device__ __align__(128) bf16  g_cl [C_DIM * N_DIM];
// zero-seeded segment end-states: [chain][seg][lane] -> float4 (hr0,hi0,hr1,hi1)
__device__ __align__(128) float4 g_st[(size_t)B_SZ * N_DIM * 2 * 32];

// ---------------------------------------------------------------------------
// Helpers (base PTX only)
// ---------------------------------------------------------------------------
__device__ __forceinline__ uint32_t smem_u32(const void* p) {
    uint32_t a;
    asm("{ .reg .u64 t; cvta.to.shared.u64 t, %1; cvt.u32.u64 %0, t; }" : "=r"(a) : "l"(p));
    return a;
}
__device__ __forceinline__ void cpa16(uint32_t d, const void* s) {
    asm volatile("cp.async.cg.shared.global [%0], [%1], 16;" :: "r"(d), "l"(s));
}
#define CP_COMMIT() asm volatile("cp.async.commit_group;" ::: "memory")
#define CP_WAIT2()  asm volatile("cp.async.wait_group 2;"  ::: "memory")

#define LDSM_X4(r0,r1,r2,r3,addr) \
    asm volatile("ldmatrix.sync.aligned.m8n8.x4.shared.b16 {%0,%1,%2,%3}, [%4];" \
        : "=r"(r0), "=r"(r1), "=r"(r2), "=r"(r3) : "r"(addr))
#define LDSM_X4T(r0,r1,r2,r3,addr) \
    asm volatile("ldmatrix.sync.aligned.m8n8.x4.trans.shared.b16 {%0,%1,%2,%3}, [%4];" \
        : "=r"(r0), "=r"(r1), "=r"(r2), "=r"(r3) : "r"(addr))

#define MMA16816(d, a, b0v, b1v) \
    asm volatile("mma.sync.aligned.m16n8k16.row.col.f32.bf16.bf16.f32 " \
        "{%0,%1,%2,%3}, {%4,%5,%6,%7}, {%8,%9}, {%0,%1,%2,%3};" \
        : "+f"((d)[0]), "+f"((d)[1]), "+f"((d)[2]), "+f"((d)[3]) \
        : "r"((a)[0]), "r"((a)[1]), "r"((a)[2]), "r"((a)[3]), "r"(b0v), "r"(b1v))

// ---------------------------------------------------------------------------
// fp32 -> bf16 hi/lo split (pre-pass)
// ---------------------------------------------------------------------------
__global__ __launch_bounds__(256) void split_fp32(
    const float* __restrict__ src, bf16* __restrict__ hi, bf16* __restrict__ lo, int n)
{
    int i = (blockIdx.x * 256 + threadIdx.x) * 4;
    if (i >= n) return;
    float4 v = *(const float4*)(src + i);
    bf16 h0 = __float2bfloat16_rn(v.x), h1 = __float2bfloat16_rn(v.y);
    bf16 h2 = __float2bfloat16_rn(v.z), h3 = __float2bfloat16_rn(v.w);
    bf16 l0 = __float2bfloat16_rn(v.x - __bfloat162float(h0));
    bf16 l1 = __float2bfloat16_rn(v.y - __bfloat162float(h1));
    bf16 l2 = __float2bfloat16_rn(v.z - __bfloat162float(h2));
    bf16 l3 = __float2bfloat16_rn(v.w - __bfloat162float(h3));
    ((__nv_bfloat162*)(hi + i))[0] = __nv_bfloat162(h0, h1);
    ((__nv_bfloat162*)(hi + i))[1] = __nv_bfloat162(h2, h3);
    ((__nv_bfloat162*)(lo + i))[0] = __nv_bfloat162(l0, l1);
    ((__nv_bfloat162*)(lo + i))[1] = __nv_bfloat162(l2, l3);
}

// ---------------------------------------------------------------------------
// HMMA GEMM (unchanged, proven 142us): Out[b] = W(512x512) @ X[b](512x8192)
// ---------------------------------------------------------------------------
#define STAGE  18432
#define A_BYTES 10240
#define NCHUNK 48
#define GEMM_SMEM (4 * STAGE)

__global__ __launch_bounds__(256, 2) void hgemm(
    const bf16* __restrict__ Ah, const bf16* __restrict__ Al,
    const bf16* __restrict__ Bh0, const bf16* __restrict__ Bl0,
    float* __restrict__ Out)
{
    extern __shared__ char smem[];
    const uint32_t sb = smem_u32(smem);
    const int tid  = threadIdx.x;
    const int lane = tid & 31, wid = tid >> 5;
    const int n0 = blockIdx.x * 128;
    const int m0 = blockIdx.y * 128;
    const bf16* Bh = Bh0 + (size_t)blockIdx.z * C_DIM * L_DIM;
    const bf16* Bl = Bl0 + (size_t)blockIdx.z * C_DIM * L_DIM;
    float* Ob = Out + (size_t)blockIdx.z * N_DIM * L_DIM;

    const int am = tid >> 2, ac = tid & 3;
    const int bk = tid >> 4, bc = tid & 15;

    auto load_stage = [&](int cl, int st) {
        if (cl < NCHUNK) {
            const bf16* As = (cl < 32) ? Ah : Al;
            const bf16* Bs = (cl >= 16 && cl < 32) ? Bl : Bh;
            const int k0 = (cl & 15) << 5;
            const uint32_t s0 = sb + (uint32_t)st * STAGE;
            cpa16(s0 + am * 80 + ac * 16,
                  As + (size_t)(m0 + am) * C_DIM + k0 + ac * 8);
            cpa16(s0 + (am + 64) * 80 + ac * 16,
                  As + (size_t)(m0 + am + 64) * C_DIM + k0 + ac * 8);
            {
                int c1 = (bc & 8) | ((bc ^ (bk & 7)) & 7);
                cpa16(s0 + A_BYTES + bk * 256 + c1 * 16,
                      Bs + (size_t)(k0 + bk) * L_DIM + n0 + bc * 8);
                int k2 = bk + 16;
                int c2 = (bc & 8) | ((bc ^ (k2 & 7)) & 7);
                cpa16(s0 + A_BYTES + k2 * 256 + c2 * 16,
                      Bs + (size_t)(k0 + k2) * L_DIM + n0 + bc * 8);
            }
        }
        CP_COMMIT();
    };

    const int wm = (wid >> 2) * 64;
    const int wn = (wid & 3) * 32;
    const uint32_t a_base = (uint32_t)(wm + (lane & 15)) * 80 + ((lane >> 4) * 16);
    uint32_t b_off[2];
#pragma unroll
    for (int nt = 0; nt < 2; nt++) {
        int g  = (wn >> 3) + nt * 2 + (lane >> 4);
        int gp = (g & 8) | ((g ^ (lane & 7)) & 7);
        b_off[nt] = (uint32_t)(lane & 15) * 256 + gp * 16;
    }

    float acc[4][4][4];
#pragma unroll
    for (int mt = 0; mt < 4; mt++)
#pragma unroll
        for (int j = 0; j < 4; j++)
#pragma unroll
            for (int r = 0; r < 4; r++) acc[mt][j][r] = 0.f;

    load_stage(0, 0); load_stage(1, 1); load_stage(2, 2);

    for (int c = 0; c < NCHUNK; c++) {
        CP_WAIT2();
        __syncthreads();
        load_stage(c + 3, (c + 3) & 3);

        const uint32_t Abase = sb + (uint32_t)(c & 3) * STAGE;
        const uint32_t Bbase = Abase + A_BYTES;
#pragma unroll
        for (int kh = 0; kh < 2; kh++) {
            uint32_t a[4][4], b[2][4];
#pragma unroll
            for (int mt = 0; mt < 4; mt++)
                LDSM_X4(a[mt][0], a[mt][1], a[mt][2], a[mt][3],
                        Abase + a_base + mt * (16 * 80) + kh * 32);
#pragma unroll
            for (int nt = 0; nt < 2; nt++)
                LDSM_X4T(b[nt][0], b[nt][1], b[nt][2], b[nt][3],
                         Bbase + b_off[nt] + kh * 4096);
#pragma unroll
            for (int mt = 0; mt < 4; mt++) {
                MMA16816(acc[mt][0], a[mt], b[0][0], b[0][1]);
                MMA16816(acc[mt][1], a[mt], b[0][2], b[0][3]);
                MMA16816(acc[mt][2], a[mt], b[1][0], b[1][1]);
                MMA16816(acc[mt][3], a[mt], b[1][2], b[1][3]);
            }
        }
    }

    const int er = lane >> 2, ec = (lane & 3) * 2;
#pragma unroll
    for (int mt = 0; mt < 4; mt++) {
#pragma unroll
        for (int j = 0; j < 4; j++) {
            size_t base = (size_t)(m0 + wm + mt * 16 + er) * L_DIM + (n0 + wn + j * 8 + ec);
            *(float2*)&Ob[base]             = make_float2(acc[mt][j][0], acc[mt][j][1]);
            *(float2*)&Ob[base + 8 * L_DIM] = make_float2(acc[mt][j][2], acc[mt][j][3]);
        }
    }
}

// ---------------------------------------------------------------------------
// Scan phase A: zero-seeded lean scan of segment [seg*2048, +2048) for every
// chain (2 warps per chain). Stores end state per (chain, seg, lane).
// Scalar fp32 (proven R3 inner loop), no output writes.
// ---------------------------------------------------------------------------
__global__ __launch_bounds__(128) void scan_seed(
    const float* __restrict__ X, float4* __restrict__ St,
    const float* __restrict__ Ar, const float* __restrict__ Ai)
{
    const int lane = threadIdx.x;
    const int w = threadIdx.y;
    const int wg = blockIdx.x * 4 + w;     // 0..4095
    const int chain = wg >> 1;             // b*512 + n
    const int seg   = wg & 1;
    const int n = chain & (N_DIM - 1);

    __shared__ float xs[4][32];

    const int s0 = n * S_DIM + lane * 2;
    float2 av = *(const float2*)&Ar[s0];
    float2 wv = *(const float2*)&Ai[s0];
    const float er0 = expf(av.x), er1 = expf(av.y);
    const float lr0 = er0 * cosf(wv.x), lr1 = er1 * cosf(wv.y);
    const float li0 = er0 * sinf(wv.x), li1 = er1 * sinf(wv.y);

    float hr0 = 0.f, hi0 = 0.f, hr1 = 0.f, hi1 = 0.f;
    const float* xp = X + (size_t)chain * L_DIM + seg * SEG;

    for (int l0 = 0; l0 < SEG; l0 += 32) {
        xs[w][lane] = xp[l0 + lane];
        __syncwarp();
#pragma unroll
        for (int t = 0; t < 32; t++) {
            const float x = xs[w][t];
            float t0 = fmaf(-li0, hi0, x);
            float u0 = fmaf(lr0, hi0, li0 * hr0);
            hr0 = fmaf(lr0, hr0, t0); hi0 = u0;
            float t1 = fmaf(-li1, hi1, x);
            float u1 = fmaf(lr1, hi1, li1 * hr1);
            hr1 = fmaf(lr1, hr1, t1); hi1 = u1;
        }
        __syncwarp();
    }
    St[((size_t)chain * 2 + seg) * 32 + lane] = make_float4(hr0, hi0, hr1, hi1);
}

// ---------------------------------------------------------------------------
// Scan phase B: 2 warps per chain (one per 4096-half). Half 1 seeds with
// S(4096) = h1 + lambda^2048 (.) h0  (complex). Emits bf16 hi/lo y.
// ---------------------------------------------------------------------------
__global__ __launch_bounds__(128) void scan_main(
    const float* __restrict__ X,
    bf16* __restrict__ Yh, bf16* __restrict__ Yl,
    const float4* __restrict__ St,
    const float* __restrict__ Ar, const float* __restrict__ Ai,
    const float* __restrict__ Ew)
{
    const int lane = threadIdx.x;
    const int w = threadIdx.y;
    const int wg = blockIdx.x * 4 + w;     // 0..4095
    const int chain = wg >> 1;
    const int half  = wg & 1;
    const int n = chain & (N_DIM - 1);

    __shared__ float xs[4][32];
    __shared__ float part[4][32][33];      // conflict-free transpose buffer

    const int s0 = n * S_DIM + lane * 2;
    float2 av = *(const float2*)&Ar[s0];
    float2 wv = *(const float2*)&Ai[s0];
    float2 ev = *(const float2*)&Ew[s0];
    const float er0 = expf(av.x), er1 = expf(av.y);
    const float lr0 = er0 * cosf(wv.x), lr1 = er1 * cosf(wv.y);
    const float li0 = er0 * sinf(wv.x), li1 = er1 * sinf(wv.y);
    const float e0 = ev.x, e1 = ev.y;

    float hr0 = 0.f, hi0 = 0.f, hr1 = 0.f, hi1 = 0.f;
    if (half) {
        float4 h0 = St[((size_t)chain * 2 + 0) * 32 + lane];
        float4 h1 = St[((size_t)chain * 2 + 1) * 32 + lane];
        // lambda^2048 per mode
        float p0 = expf(2048.f * av.x), p1 = expf(2048.f * av.y);
        float g0 = 2048.f * wv.x,       g1 = 2048.f * wv.y;
        float c0 = p0 * cosf(g0), sgn0 = p0 * sinf(g0);
        float c1 = p1 * cosf(g1), sgn1 = p1 * sinf(g1);
        hr0 = h1.x + c0 * h0.x - sgn0 * h0.y;
        hi0 = h1.y + c0 * h0.y + sgn0 * h0.x;
        hr1 = h1.z + c1 * h0.z - sgn1 * h0.w;
        hi1 = h1.w + c1 * h0.w + sgn1 * h0.z;
    }

    const int base = half * HALF_L;
    const float* xp = X + (size_t)chain * L_DIM + base;
    bf16* yhp = Yh + (size_t)chain * L_DIM + base;
    bf16* ylp = Yl + (size_t)chain * L_DIM + base;

    for (int l0 = 0; l0 < HALF_L; l0 += 32) {
        xs[w][lane] = xp[l0 + lane];
        __syncwarp();
#pragma unroll
        for (int t = 0; t < 32; t++) {
            const float x = xs[w][t];
            float t0 = fmaf(-li0, hi0, x);
            float u0 = fmaf(lr0, hi0, li0 * hr0);
            hr0 = fmaf(lr0, hr0, t0); hi0 = u0;
            float t1 = fmaf(-li1, hi1, x);
            float u1 = fmaf(lr1, hi1, li1 * hr1);
            hr1 = fmaf(lr1, hr1, t1); hi1 = u1;
            part[w][t][lane] = fmaf(e0, hr0, e1 * hr1);
        }
        __syncwarp();
        float acc = 0.f;
#pragma unroll
        for (int q = 0; q < 32; q++) acc += part[w][lane][q];
        bf16 h = __float2bfloat16_rn(acc);
        yhp[l0 + lane] = h;
        ylp[l0 + lane] = __float2bfloat16_rn(acc - __bfloat162float(h));
        __syncwarp();
    }
}

// ---------------------------------------------------------------------------
extern "C" void kernel_launch(void* const* d_in, const int* in_sizes, int n_in,
                              void* d_out, int out_size)
{
    const float* inp = (const float*)d_in[0];  // [B, C, L]
    const float* ar  = (const float*)d_in[1];  // [N, S]
    const float* ai  = (const float*)d_in[2];  // [N, S]
    const float* Bm  = (const float*)d_in[3];  // [N, C]
    const float* Cm  = (const float*)d_in[4];  // [C, N]
    const float* E   = (const float*)d_in[5];  // [N, S]
    float* out = (float*)d_out;                // [B, C, L]

    float *xp;  bf16 *inh, *inl, *yh, *yl, *bh, *bl, *ch, *cl;  float4* st;
    cudaGetSymbolAddress((void**)&xp,  g_x);
    cudaGetSymbolAddress((void**)&inh, g_inh);
    cudaGetSymbolAddress((void**)&inl, g_inl);
    cudaGetSymbolAddress((void**)&yh,  g_yh);
    cudaGetSymbolAddress((void**)&yl,  g_yl);
    cudaGetSymbolAddress((void**)&bh,  g_bh);
    cudaGetSymbolAddress((void**)&bl,  g_bl);
    cudaGetSymbolAddress((void**)&ch,  g_ch);
    cudaGetSymbolAddress((void**)&cl,  g_cl);
    cudaGetSymbolAddress((void**)&st,  g_st);

    cudaFuncSetAttribute(hgemm, cudaFuncAttributeMaxDynamicSharedMemorySize, GEMM_SMEM);

    const int n_in_elems = B_SZ * C_DIM * L_DIM;
    const int n_w = C_DIM * N_DIM;

    split_fp32<<<n_in_elems / 1024, 256>>>(inp, inh, inl, n_in_elems);
    split_fp32<<<n_w / 1024, 256>>>(Bm, bh, bl, n_w);
    split_fp32<<<n_w / 1024, 256>>>(Cm, ch, cl, n_w);

    dim3 gg(L_DIM / 128, N_DIM / 128, B_SZ);
    hgemm<<<gg, 256, GEMM_SMEM>>>(bh, bl, inh, inl, xp);                   // x = B @ input
    scan_seed<<<(B_SZ * N_DIM * 2) / 4, dim3(32, 4)>>>(xp, st, ar, ai);    // segment end-states
    scan_main<<<(B_SZ * N_DIM * 2) / 4, dim3(32, 4)>>>(xp, yh, yl, st, ar, ai, E);
    hgemm<<<gg, 256, GEMM_SMEM>>>(ch, cl, yh, yl, out);                    // out = C @ y
}

// round 6
// speedup vs baseline: 1.3136x; 1.1285x over previous
#include <cuda_runtime.h>
#include <cuda_bf16.h>
#include <cstdint>
#include <math.h>

#define B_SZ   4
#define C_DIM  512
#define N_DIM  512
#define S_DIM  64
#define L_DIM  8192
#define T_CH   64      // chunk length
#define NCHK   128     // chunks per chain

typedef __nv_bfloat16 bf16;

// ---------------------------------------------------------------------------
// Scratch (allocation-free rule: __device__ globals)
// ---------------------------------------------------------------------------
__device__ __align__(128) bf16  g_inh[(size_t)B_SZ * C_DIM * L_DIM];
__device__ __align__(128) bf16  g_inl[(size_t)B_SZ * C_DIM * L_DIM];
__device__ __align__(128) bf16  g_xh [(size_t)B_SZ * N_DIM * L_DIM];   // gemm1 out (split)
__device__ __align__(128) bf16  g_xl [(size_t)B_SZ * N_DIM * L_DIM];
__device__ __align__(128) bf16  g_yh [(size_t)B_SZ * N_DIM * L_DIM];   // conv out (split)
__device__ __align__(128) bf16  g_yl [(size_t)B_SZ * N_DIM * L_DIM];
__device__ __align__(128) bf16  g_bh [C_DIM * N_DIM];
__device__ __align__(128) bf16  g_bl [C_DIM * N_DIM];
__device__ __align__(128) bf16  g_ch [C_DIM * N_DIM];
__device__ __align__(128) bf16  g_cl [C_DIM * N_DIM];
// per-channel conv weights: [n][k=192][t=64]  (k<64: Toeplitz rows, k>=64: basis)
__device__ __align__(128) bf16  g_wbh[(size_t)N_DIM * 192 * 64];
__device__ __align__(128) bf16  g_wbl[(size_t)N_DIM * 192 * 64];
// per-channel contribution weights: [n][i=64][mode=128]
__device__ __align__(128) bf16  g_wch[(size_t)N_DIM * 64 * 128];
__device__ __align__(128) bf16  g_wcl[(size_t)N_DIM * 64 * 128];
// chunk contributions: [chain][chunk=128][mode=128] fp32
__device__ __align__(128) float g_c  [(size_t)B_SZ * N_DIM * NCHK * 128];
// chunk-boundary states (h_pre, split): [chain][chunk=128][mode=128]
__device__ __align__(128) bf16  g_hh [(size_t)B_SZ * N_DIM * NCHK * 128];
__device__ __align__(128) bf16  g_hl [(size_t)B_SZ * N_DIM * NCHK * 128];

// ---------------------------------------------------------------------------
// Helpers (base PTX only)
// ---------------------------------------------------------------------------
__device__ __forceinline__ uint32_t smem_u32(const void* p) {
    uint32_t a;
    asm("{ .reg .u64 t; cvta.to.shared.u64 t, %1; cvt.u32.u64 %0, t; }" : "=r"(a) : "l"(p));
    return a;
}
__device__ __forceinline__ void cpa16(uint32_t d, const void* s) {
    asm volatile("cp.async.cg.shared.global [%0], [%1], 16;" :: "r"(d), "l"(s));
}
#define CP_COMMIT() asm volatile("cp.async.commit_group;" ::: "memory")
#define CP_WAIT2()  asm volatile("cp.async.wait_group 2;"  ::: "memory")

#define LDSM_X4(r0,r1,r2,r3,addr) \
    asm volatile("ldmatrix.sync.aligned.m8n8.x4.shared.b16 {%0,%1,%2,%3}, [%4];" \
        : "=r"(r0), "=r"(r1), "=r"(r2), "=r"(r3) : "r"(addr))
#define LDSM_X4T(r0,r1,r2,r3,addr) \
    asm volatile("ldmatrix.sync.aligned.m8n8.x4.trans.shared.b16 {%0,%1,%2,%3}, [%4];" \
        : "=r"(r0), "=r"(r1), "=r"(r2), "=r"(r3) : "r"(addr))

#define MMA16816(d, a, b0v, b1v) \
    asm volatile("mma.sync.aligned.m16n8k16.row.col.f32.bf16.bf16.f32 " \
        "{%0,%1,%2,%3}, {%4,%5,%6,%7}, {%8,%9}, {%0,%1,%2,%3};" \
        : "+f"((d)[0]), "+f"((d)[1]), "+f"((d)[2]), "+f"((d)[3]) \
        : "r"((a)[0]), "r"((a)[1]), "r"((a)[2]), "r"((a)[3]), "r"(b0v), "r"(b1v))

__device__ __forceinline__ void split1(float v, bf16& h, bf16& l) {
    h = __float2bfloat16_rn(v);
    l = __float2bfloat16_rn(v - __bfloat162float(h));
}

// ---------------------------------------------------------------------------
// fp32 -> bf16 hi/lo split (pre-pass)
// ---------------------------------------------------------------------------
__global__ __launch_bounds__(256) void split_fp32(
    const float* __restrict__ src, bf16* __restrict__ hi, bf16* __restrict__ lo, int n)
{
    int i = (blockIdx.x * 256 + threadIdx.x) * 4;
    if (i >= n) return;
    float4 v = *(const float4*)(src + i);
    bf16 h0, l0, h1, l1, h2, l2, h3, l3;
    split1(v.x, h0, l0); split1(v.y, h1, l1);
    split1(v.z, h2, l2); split1(v.w, h3, l3);
    ((__nv_bfloat162*)(hi + i))[0] = __nv_bfloat162(h0, h1);
    ((__nv_bfloat162*)(hi + i))[1] = __nv_bfloat162(h2, h3);
    ((__nv_bfloat162*)(lo + i))[0] = __nv_bfloat162(l0, l1);
    ((__nv_bfloat162*)(lo + i))[1] = __nv_bfloat162(l2, l3);
}

// ---------------------------------------------------------------------------
// HMMA GEMM: Out[b] = W(512x512) @ X[b](512x8192), fp32 via 3-term bf16 split.
// If OutF != nullptr -> fp32 out, else split bf16 out to OutH/OutL.
// ---------------------------------------------------------------------------
#define STAGE   18432
#define A_BYTES 10240
#define NCHUNK  48
#define GEMM_SMEM (4 * STAGE)

__global__ __launch_bounds__(256, 2) void hgemm(
    const bf16* __restrict__ Ah, const bf16* __restrict__ Al,
    const bf16* __restrict__ Bh0, const bf16* __restrict__ Bl0,
    float* __restrict__ OutF, bf16* __restrict__ OutH, bf16* __restrict__ OutL)
{
    extern __shared__ char smem[];
    const uint32_t sb = smem_u32(smem);
    const int tid  = threadIdx.x;
    const int lane = tid & 31, wid = tid >> 5;
    const int n0 = blockIdx.x * 128;
    const int m0 = blockIdx.y * 128;
    const size_t boff = (size_t)blockIdx.z * C_DIM * L_DIM;
    const bf16* Bh = Bh0 + boff;
    const bf16* Bl = Bl0 + boff;

    const int am = tid >> 2, ac = tid & 3;
    const int bk = tid >> 4, bc = tid & 15;

    auto load_stage = [&](int cl, int st) {
        if (cl < NCHUNK) {
            const bf16* As = (cl < 32) ? Ah : Al;
            const bf16* Bs = (cl >= 16 && cl < 32) ? Bl : Bh;
            const int k0 = (cl & 15) << 5;
            const uint32_t s0 = sb + (uint32_t)st * STAGE;
            cpa16(s0 + am * 80 + ac * 16,
                  As + (size_t)(m0 + am) * C_DIM + k0 + ac * 8);
            cpa16(s0 + (am + 64) * 80 + ac * 16,
                  As + (size_t)(m0 + am + 64) * C_DIM + k0 + ac * 8);
            {
                int c1 = (bc & 8) | ((bc ^ (bk & 7)) & 7);
                cpa16(s0 + A_BYTES + bk * 256 + c1 * 16,
                      Bs + (size_t)(k0 + bk) * L_DIM + n0 + bc * 8);
                int k2 = bk + 16;
                int c2 = (bc & 8) | ((bc ^ (k2 & 7)) & 7);
                cpa16(s0 + A_BYTES + k2 * 256 + c2 * 16,
                      Bs + (size_t)(k0 + k2) * L_DIM + n0 + bc * 8);
            }
        }
        CP_COMMIT();
    };

    const int wm = (wid >> 2) * 64;
    const int wn = (wid & 3) * 32;
    const uint32_t a_base = (uint32_t)(wm + (lane & 15)) * 80 + ((lane >> 4) * 16);
    uint32_t b_off[2];
#pragma unroll
    for (int nt = 0; nt < 2; nt++) {
        int g  = (wn >> 3) + nt * 2 + (lane >> 4);
        int gp = (g & 8) | ((g ^ (lane & 7)) & 7);
        b_off[nt] = (uint32_t)(lane & 15) * 256 + gp * 16;
    }

    float acc[4][4][4];
#pragma unroll
    for (int mt = 0; mt < 4; mt++)
#pragma unroll
        for (int j = 0; j < 4; j++)
#pragma unroll
            for (int r = 0; r < 4; r++) acc[mt][j][r] = 0.f;

    load_stage(0, 0); load_stage(1, 1); load_stage(2, 2);

    for (int c = 0; c < NCHUNK; c++) {
        CP_WAIT2();
        __syncthreads();
        load_stage(c + 3, (c + 3) & 3);

        const uint32_t Abase = sb + (uint32_t)(c & 3) * STAGE;
        const uint32_t Bbase = Abase + A_BYTES;
#pragma unroll
        for (int kh = 0; kh < 2; kh++) {
            uint32_t a[4][4], b[2][4];
#pragma unroll
            for (int mt = 0; mt < 4; mt++)
                LDSM_X4(a[mt][0], a[mt][1], a[mt][2], a[mt][3],
                        Abase + a_base + mt * (16 * 80) + kh * 32);
#pragma unroll
            for (int nt = 0; nt < 2; nt++)
                LDSM_X4T(b[nt][0], b[nt][1], b[nt][2], b[nt][3],
                         Bbase + b_off[nt] + kh * 4096);
#pragma unroll
            for (int mt = 0; mt < 4; mt++) {
                MMA16816(acc[mt][0], a[mt], b[0][0], b[0][1]);
                MMA16816(acc[mt][1], a[mt], b[0][2], b[0][3]);
                MMA16816(acc[mt][2], a[mt], b[1][0], b[1][1]);
                MMA16816(acc[mt][3], a[mt], b[1][2], b[1][3]);
            }
        }
    }

    const int er = lane >> 2, ec = (lane & 3) * 2;
    const size_t outz = (size_t)blockIdx.z * N_DIM * L_DIM;
#pragma unroll
    for (int mt = 0; mt < 4; mt++) {
#pragma unroll
        for (int j = 0; j < 4; j++) {
            size_t base = outz + (size_t)(m0 + wm + mt * 16 + er) * L_DIM + (n0 + wn + j * 8 + ec);
            if (OutF) {
                *(float2*)&OutF[base]             = make_float2(acc[mt][j][0], acc[mt][j][1]);
                *(float2*)&OutF[base + 8 * L_DIM] = make_float2(acc[mt][j][2], acc[mt][j][3]);
            } else {
                bf16 h0, l0, h1, l1;
                split1(acc[mt][j][0], h0, l0); split1(acc[mt][j][1], h1, l1);
                *(__nv_bfloat162*)&OutH[base] = __nv_bfloat162(h0, h1);
                *(__nv_bfloat162*)&OutL[base] = __nv_bfloat162(l0, l1);
                split1(acc[mt][j][2], h0, l0); split1(acc[mt][j][3], h1, l1);
                *(__nv_bfloat162*)&OutH[base + 8 * L_DIM] = __nv_bfloat162(h0, h1);
                *(__nv_bfloat162*)&OutL[base + 8 * L_DIM] = __nv_bfloat162(l0, l1);
            }
        }
    }
}

// ---------------------------------------------------------------------------
// Prep: per channel n build
//   Wc^T[i][2s]=Re(lam^{63-i}), [2s+1]=Im(lam^{63-i})              (contrib)
//   Wb[k<64][t]  = K[t-k] (t>=k) Toeplitz rows,  K[d]=Sum_s E Re(lam^d)
//   Wb[64+2s][t] = E Re(lam^{t+1}),  Wb[65+2s][t] = -E Im(lam^{t+1})
// One block per channel, 64 threads (one per mode).
// ---------------------------------------------------------------------------
__global__ __launch_bounds__(64) void prep_weights(
    const float* __restrict__ Ar, const float* __restrict__ Ai,
    const float* __restrict__ Ew,
    bf16* __restrict__ wbh, bf16* __restrict__ wbl,
    bf16* __restrict__ wch, bf16* __restrict__ wcl)
{
    const int n = blockIdx.x;
    const int s = threadIdx.x;
    __shared__ float p[64][65];
    __shared__ float K[64];

    const float a = Ar[n * 64 + s], w = Ai[n * 64 + s], E = Ew[n * 64 + s];
    const float er = expf(a);
    const float lr = er * cosf(w), li = er * sinf(w);

    float cr = 1.f, ci = 0.f;   // lambda^d
    for (int d = 0; d <= 64; d++) {
        if (d < 64) {
            p[d][s] = E * cr;
            int i = 63 - d;
            bf16 h, l;
            size_t wci = ((size_t)n * 64 + i) * 128;
            split1(cr, h, l); wch[wci + 2*s]   = h; wcl[wci + 2*s]   = l;
            split1(ci, h, l); wch[wci + 2*s+1] = h; wcl[wci + 2*s+1] = l;
        }
        if (d >= 1) {
            int t = d - 1;
            bf16 h, l;
            size_t b0 = ((size_t)n * 192 + 64 + 2*s) * 64 + t;
            size_t b1 = ((size_t)n * 192 + 65 + 2*s) * 64 + t;
            split1(E * cr,  h, l); wbh[b0] = h; wbl[b0] = l;
            split1(-E * ci, h, l); wbh[b1] = h; wbl[b1] = l;
        }
        float nr = cr * lr - ci * li;
        float ni = cr * li + ci * lr;
        cr = nr; ci = ni;
    }
    __syncthreads();
    {
        float acc = 0.f;
#pragma unroll
        for (int q = 0; q < 64; q++) acc += p[s][q];
        K[s] = acc;
    }
    __syncthreads();
    // Toeplitz rows: thread s = row k
    for (int t = 0; t < 64; t++) {
        float v = (t >= s) ? K[t - s] : 0.f;
        bf16 h, l; split1(v, h, l);
        size_t idx = ((size_t)n * 192 + s) * 64 + t;
        wbh[idx] = h; wbl[idx] = l;
    }
}

// ---------------------------------------------------------------------------
// Contribution GEMM: per (batch, channel):
//   Cc[j][mode] = Sum_i x[chain][j*64+i] * Wc^T[i][mode]
// M=128 (chunks j), N=128 (modes), K=64 (3-term split -> 6 virtual chunks).
// Clone of hgemm structure (same stage layout).
// ---------------------------------------------------------------------------
#define CN_CHUNK 6
__global__ __launch_bounds__(256, 2) void contrib_gemm(
    const bf16* __restrict__ Xh, const bf16* __restrict__ Xl,
    const bf16* __restrict__ Wh, const bf16* __restrict__ Wl,
    float* __restrict__ Cc)
{
    extern __shared__ char smem[];
    const uint32_t sb = smem_u32(smem);
    const int tid  = threadIdx.x;
    const int lane = tid & 31, wid = tid >> 5;
    const int bb = blockIdx.x;          // batch
    const int n  = blockIdx.y;          // channel
    const size_t chain = (size_t)bb * N_DIM + n;

    const int am = tid >> 2, ac = tid & 3;
    const int bk = tid >> 4, bc = tid & 15;

    auto load_stage = [&](int cl, int st) {
        if (cl < CN_CHUNK) {
            const bf16* As = (cl < 4) ? Xh : Xl;
            const bf16* Bs = (cl >= 2 && cl < 4) ? Wl : Wh;
            const int khalf = (cl & 1) * 32;
            const uint32_t s0 = sb + (uint32_t)st * STAGE;
            // A: 128 rows (j) x 32 k, rows am and am+64
            cpa16(s0 + am * 80 + ac * 16,
                  As + chain * L_DIM + (size_t)am * 64 + khalf + ac * 8);
            cpa16(s0 + (am + 64) * 80 + ac * 16,
                  As + chain * L_DIM + (size_t)(am + 64) * 64 + khalf + ac * 8);
            // B: 32 rows (k) x 128 modes, 256B rows, hgemm swizzle
            {
                int c1 = (bc & 8) | ((bc ^ (bk & 7)) & 7);
                cpa16(s0 + A_BYTES + bk * 256 + c1 * 16,
                      Bs + ((size_t)n * 64 + khalf + bk) * 128 + bc * 8);
                int k2 = bk + 16;
                int c2 = (bc & 8) | ((bc ^ (k2 & 7)) & 7);
                cpa16(s0 + A_BYTES + k2 * 256 + c2 * 16,
                      Bs + ((size_t)n * 64 + khalf + k2) * 128 + bc * 8);
            }
        }
        CP_COMMIT();
    };

    const int wm = (wid >> 2) * 64;
    const int wn = (wid & 3) * 32;
    const uint32_t a_base = (uint32_t)(wm + (lane & 15)) * 80 + ((lane >> 4) * 16);
    uint32_t b_off[2];
#pragma unroll
    for (int nt = 0; nt < 2; nt++) {
        int g  = (wn >> 3) + nt * 2 + (lane >> 4);
        int gp = (g & 8) | ((g ^ (lane & 7)) & 7);
        b_off[nt] = (uint32_t)(lane & 15) * 256 + gp * 16;
    }

    float acc[4][4][4];
#pragma unroll
    for (int mt = 0; mt < 4; mt++)
#pragma unroll
        for (int j = 0; j < 4; j++)
#pragma unroll
            for (int r = 0; r < 4; r++) acc[mt][j][r] = 0.f;

    load_stage(0, 0); load_stage(1, 1); load_stage(2, 2);

    for (int c = 0; c < CN_CHUNK; c++) {
        CP_WAIT2();
        __syncthreads();
        load_stage(c + 3, (c + 3) & 3);

        const uint32_t Abase = sb + (uint32_t)(c & 3) * STAGE;
        const uint32_t Bbase = Abase + A_BYTES;
#pragma unroll
        for (int kh = 0; kh < 2; kh++) {
            uint32_t a[4][4], b[2][4];
#pragma unroll
            for (int mt = 0; mt < 4; mt++)
                LDSM_X4(a[mt][0], a[mt][1], a[mt][2], a[mt][3],
                        Abase + a_base + mt * (16 * 80) + kh * 32);
#pragma unroll
            for (int nt = 0; nt < 2; nt++)
                LDSM_X4T(b[nt][0], b[nt][1], b[nt][2], b[nt][3],
                         Bbase + b_off[nt] + kh * 4096);
#pragma unroll
            for (int mt = 0; mt < 4; mt++) {
                MMA16816(acc[mt][0], a[mt], b[0][0], b[0][1]);
                MMA16816(acc[mt][1], a[mt], b[0][2], b[0][3]);
                MMA16816(acc[mt][2], a[mt], b[1][0], b[1][1]);
                MMA16816(acc[mt][3], a[mt], b[1][2], b[1][3]);
            }
        }
    }

    const int er = lane >> 2, ec = (lane & 3) * 2;
    float* Cp = Cc + chain * NCHK * 128;
#pragma unroll
    for (int mt = 0; mt < 4; mt++) {
#pragma unroll
        for (int j = 0; j < 4; j++) {
            size_t base = (size_t)(wm + mt * 16 + er) * 128 + (wn + j * 8 + ec);
            *(float2*)&Cp[base]           = make_float2(acc[mt][j][0], acc[mt][j][1]);
            *(float2*)&Cp[base + 8 * 128] = make_float2(acc[mt][j][2], acc[mt][j][3]);
        }
    }
}

// ---------------------------------------------------------------------------
// Chunk state scan (tiny sequential): per chain, 128 chunk steps.
//   Hpre[j] = H;  H = Lam64 (.) H + Cc[j]
// Stores Hpre split bf16 [chain][j][mode].
// ---------------------------------------------------------------------------
__global__ __launch_bounds__(128) void chunk_scan(
    const float* __restrict__ Cc, bf16* __restrict__ Hh, bf16* __restrict__ Hl,
    const float* __restrict__ Ar, const float* __restrict__ Ai)
{
    const int lane = threadIdx.x;
    const int w = threadIdx.y;
    const size_t chain = (size_t)blockIdx.x * 4 + w;
    const int n = (int)(chain & (N_DIM - 1));

    const int s0 = n * S_DIM + lane * 2;
    float2 av = *(const float2*)&Ar[s0];
    float2 wv = *(const float2*)&Ai[s0];
    const float p0 = expf(64.f * av.x), p1 = expf(64.f * av.y);
    const float g0 = 64.f * wv.x,       g1 = 64.f * wv.y;
    const float c640 = p0 * cosf(g0), s640 = p0 * sinf(g0);
    const float c641 = p1 * cosf(g1), s641 = p1 * sinf(g1);

    float hr0 = 0.f, hi0 = 0.f, hr1 = 0.f, hi1 = 0.f;
    const float* cp = Cc + chain * NCHK * 128;
    bf16* hhp = Hh + chain * NCHK * 128;
    bf16* hlp = Hl + chain * NCHK * 128;

    for (int j = 0; j < NCHK; j++) {
        bf16 a0, b0, a1, b1, a2, b2, a3, b3;
        split1(hr0, a0, b0); split1(hi0, a1, b1);
        split1(hr1, a2, b2); split1(hi1, a3, b3);
        size_t o = (size_t)j * 128 + lane * 4;
        *(__nv_bfloat162*)&hhp[o]     = __nv_bfloat162(a0, a1);
        *(__nv_bfloat162*)&hhp[o + 2] = __nv_bfloat162(a2, a3);
        *(__nv_bfloat162*)&hlp[o]     = __nv_bfloat162(b0, b1);
        *(__nv_bfloat162*)&hlp[o + 2] = __nv_bfloat162(b2, b3);
        float4 cv = *(const float4*)&cp[(size_t)j * 128 + lane * 4];
        float nr0 = c640 * hr0 - s640 * hi0 + cv.x;
        float ni0 = c640 * hi0 + s640 * hr0 + cv.y;
        float nr1 = c641 * hr1 - s641 * hi1 + cv.z;
        float ni1 = c641 * hi1 + s641 * hr1 + cv.w;
        hr0 = nr0; hi0 = ni0; hr1 = nr1; hi1 = ni1;
    }
}

// ---------------------------------------------------------------------------
// Conv GEMM: per (batch, channel):
//   y[j][t] = Sum_{k<64} x_j[k] K[t-k]  +  Sum_modes Hpre[j][m] Basis[m][t]
// M=128 (chunks j), N=64 (t), K=192 (3-term split -> 18 virtual chunks of 32).
// A rows: k<64 from xh/xl, k>=64 from Hh/Hl. B rows 128B, 8-chunk XOR swizzle.
// Emits y split bf16 into yh/yl [chain][l].
// ---------------------------------------------------------------------------
#define VB_BYTES 4096
#define VSTAGE   (A_BYTES + VB_BYTES)      // 14336
#define VN_CHUNK 18
#define CONV_SMEM (4 * VSTAGE)

__global__ __launch_bounds__(256, 2) void conv_gemm(
    const bf16* __restrict__ Xh, const bf16* __restrict__ Xl,
    const bf16* __restrict__ Hh, const bf16* __restrict__ Hl,
    const bf16* __restrict__ Wh, const bf16* __restrict__ Wl,
    bf16* __restrict__ Yh, bf16* __restrict__ Yl)
{
    extern __shared__ char smem[];
    const uint32_t sb = smem_u32(smem);
    const int tid  = threadIdx.x;
    const int lane = tid & 31, wid = tid >> 5;
    const int bb = blockIdx.x;
    const int n  = blockIdx.y;
    const size_t chain = (size_t)bb * N_DIM + n;

    const int am = tid >> 2, ac = tid & 3;
    const int vk = tid >> 3, vc = tid & 7;      // B loader: 32 rows x 8 chunks

    auto load_stage = [&](int cl, int st) {
        if (cl < VN_CHUNK) {
            const int term = cl / 6, kc = cl % 6;
            const uint32_t s0 = sb + (uint32_t)st * VSTAGE;
            // A chunk: 128 rows x 32 k
            const bf16* rowsrc;
            size_t rstride, roff;
            if (kc < 2) {
                rowsrc = (term < 2) ? Xh : Xl;
                rowsrc += chain * L_DIM;
                rstride = 64; roff = (size_t)kc * 32;
            } else {
                rowsrc = (term < 2) ? Hh : Hl;
                rowsrc += chain * NCHK * 128;
                rstride = 128; roff = (size_t)(kc - 2) * 32;
            }
            cpa16(s0 + am * 80 + ac * 16,
                  rowsrc + (size_t)am * rstride + roff + ac * 8);
            cpa16(s0 + (am + 64) * 80 + ac * 16,
                  rowsrc + (size_t)(am + 64) * rstride + roff + ac * 8);
            // B chunk: 32 rows x 64 t (128B rows), xor swizzle
            const bf16* Bs = (term == 1) ? Wl : Wh;
            int cp = vc ^ (vk & 7);
            cpa16(s0 + A_BYTES + vk * 128 + cp * 16,
                  Bs + ((size_t)n * 192 + (size_t)kc * 32 + vk) * 64 + vc * 8);
        }
        CP_COMMIT();
    };

    const int wm = (wid >> 2) * 64;      // M: 2 groups of 64
    const int wn = (wid & 3) * 16;       // N: 4 groups of 16
    const uint32_t a_base = (uint32_t)(wm + (lane & 15)) * 80 + ((lane >> 4) * 16);

    float acc[4][2][4];
#pragma unroll
    for (int mt = 0; mt < 4; mt++)
#pragma unroll
        for (int j = 0; j < 2; j++)
#pragma unroll
            for (int r = 0; r < 4; r++) acc[mt][j][r] = 0.f;

    load_stage(0, 0); load_stage(1, 1); load_stage(2, 2);

    for (int c = 0; c < VN_CHUNK; c++) {
        CP_WAIT2();
        __syncthreads();
        load_stage(c + 3, (c + 3) & 3);

        const uint32_t Abase = sb + (uint32_t)(c & 3) * VSTAGE;
        const uint32_t Bbase = Abase + A_BYTES;
#pragma unroll
        for (int kh = 0; kh < 2; kh++) {
            uint32_t a[4][4], b[4];
#pragma unroll
            for (int mt = 0; mt < 4; mt++)
                LDSM_X4(a[mt][0], a[mt][1], a[mt][2], a[mt][3],
                        Abase + a_base + mt * (16 * 80) + kh * 32);
            {
                int krow = kh * 16 + (lane & 15);
                int g = (wn >> 3) + (lane >> 4);
                uint32_t boff = (uint32_t)krow * 128 + (uint32_t)(((g ^ (krow & 7)) & 7) * 16);
                LDSM_X4T(b[0], b[1], b[2], b[3], Bbase + boff);
            }
#pragma unroll
            for (int mt = 0; mt < 4; mt++) {
                MMA16816(acc[mt][0], a[mt], b[0], b[1]);
                MMA16816(acc[mt][1], a[mt], b[2], b[3]);
            }
        }
    }

    const int er = lane >> 2, ec = (lane & 3) * 2;
    bf16* yhp = Yh + chain * L_DIM;
    bf16* ylp = Yl + chain * L_DIM;
#pragma unroll
    for (int mt = 0; mt < 4; mt++) {
#pragma unroll
        for (int j = 0; j < 2; j++) {
            int row0 = wm + mt * 16 + er;        // chunk index j
            int tcol = wn + j * 8 + ec;
            size_t b0 = (size_t)row0 * 64 + tcol;
            bf16 h0, l0, h1, l1;
            split1(acc[mt][j][0], h0, l0); split1(acc[mt][j][1], h1, l1);
            *(__nv_bfloat162*)&yhp[b0] = __nv_bfloat162(h0, h1);
            *(__nv_bfloat162*)&ylp[b0] = __nv_bfloat162(l0, l1);
            size_t b1 = (size_t)(row0 + 8) * 64 + tcol;
            split1(acc[mt][j][2], h0, l0); split1(acc[mt][j][3], h1, l1);
            *(__nv_bfloat162*)&yhp[b1] = __nv_bfloat162(h0, h1);
            *(__nv_bfloat162*)&ylp[b1] = __nv_bfloat162(l0, l1);
        }
    }
}

// ---------------------------------------------------------------------------
extern "C" void kernel_launch(void* const* d_in, const int* in_sizes, int n_in,
                              void* d_out, int out_size)
{
    const float* inp = (const float*)d_in[0];  // [B, C, L]
    const float* ar  = (const float*)d_in[1];  // [N, S]
    const float* ai  = (const float*)d_in[2];  // [N, S]
    const float* Bm  = (const float*)d_in[3];  // [N, C]
    const float* Cm  = (const float*)d_in[4];  // [C, N]
    const float* E   = (const float*)d_in[5];  // [N, S]
    float* out = (float*)d_out;                // [B, C, L]

    bf16 *inh, *inl, *xh, *xl, *yh, *yl, *bh, *bl, *ch, *cl;
    bf16 *wbh, *wbl, *wch, *wcl, *hh, *hl;
    float *cc;
    cudaGetSymbolAddress((void**)&inh, g_inh);
    cudaGetSymbolAddress((void**)&inl, g_inl);
    cudaGetSymbolAddress((void**)&xh,  g_xh);
    cudaGetSymbolAddress((void**)&xl,  g_xl);
    cudaGetSymbolAddress((void**)&yh,  g_yh);
    cudaGetSymbolAddress((void**)&yl,  g_yl);
    cudaGetSymbolAddress((void**)&bh,  g_bh);
    cudaGetSymbolAddress((void**)&bl,  g_bl);
    cudaGetSymbolAddress((void**)&ch,  g_ch);
    cudaGetSymbolAddress((void**)&cl,  g_cl);
    cudaGetSymbolAddress((void**)&wbh, g_wbh);
    cudaGetSymbolAddress((void**)&wbl, g_wbl);
    cudaGetSymbolAddress((void**)&wch, g_wch);
    cudaGetSymbolAddress((void**)&wcl, g_wcl);
    cudaGetSymbolAddress((void**)&hh,  g_hh);
    cudaGetSymbolAddress((void**)&hl,  g_hl);
    cudaGetSymbolAddress((void**)&cc,  g_c);

    cudaFuncSetAttribute(hgemm,        cudaFuncAttributeMaxDynamicSharedMemorySize, GEMM_SMEM);
    cudaFuncSetAttribute(contrib_gemm, cudaFuncAttributeMaxDynamicSharedMemorySize, GEMM_SMEM);
    cudaFuncSetAttribute(conv_gemm,    cudaFuncAttributeMaxDynamicSharedMemorySize, CONV_SMEM);

    const int n_in_elems = B_SZ * C_DIM * L_DIM;
    const int n_w = C_DIM * N_DIM;

    split_fp32<<<n_in_elems / 1024, 256>>>(inp, inh, inl, n_in_elems);
    split_fp32<<<n_w / 1024, 256>>>(Bm, bh, bl, n_w);
    split_fp32<<<n_w / 1024, 256>>>(Cm, ch, cl, n_w);
    prep_weights<<<N_DIM, 64>>>(ar, ai, E, wbh, wbl, wch, wcl);

    dim3 gg(L_DIM / 128, N_DIM / 128, B_SZ);
    hgemm<<<gg, 256, GEMM_SMEM>>>(bh, bl, inh, inl, nullptr, xh, xl);   // x = B@input (split out)

    contrib_gemm<<<dim3(B_SZ, N_DIM), 256, GEMM_SMEM>>>(xh, xl, wch, wcl, cc);
    chunk_scan<<<(B_SZ * N_DIM) / 4, dim3(32, 4)>>>(cc, hh, hl, ar, ai);
    conv_gemm<<<dim3(B_SZ, N_DIM), 256, CONV_SMEM>>>(xh, xl, hh, hl, wbh, wbl, yh, yl);

    hgemm<<<gg, 256, GEMM_SMEM>>>(ch, cl, yh, yl, out, nullptr, nullptr); // out = C@y
}

// round 7
// speedup vs baseline: 1.6128x; 1.2278x over previous
#include <cuda_runtime.h>
#include <cuda_bf16.h>
#include <cstdint>
#include <math.h>

#define B_SZ   4
#define C_DIM  512
#define N_DIM  512
#define S_DIM  64
#define L_DIM  8192
#define T_CH   64      // chunk length
#define NCHK   128     // chunks per chain

typedef __nv_bfloat16 bf16;

// ---------------------------------------------------------------------------
// Scratch (allocation-free rule: __device__ globals)
// ---------------------------------------------------------------------------
__device__ __align__(128) bf16  g_inh[(size_t)B_SZ * C_DIM * L_DIM];
__device__ __align__(128) bf16  g_inl[(size_t)B_SZ * C_DIM * L_DIM];
__device__ __align__(128) bf16  g_xh [(size_t)B_SZ * N_DIM * L_DIM];   // gemm1 out (split)
__device__ __align__(128) bf16  g_xl [(size_t)B_SZ * N_DIM * L_DIM];
__device__ __align__(128) bf16  g_yh [(size_t)B_SZ * N_DIM * L_DIM];   // conv out (split)
__device__ __align__(128) bf16  g_yl [(size_t)B_SZ * N_DIM * L_DIM];
__device__ __align__(128) bf16  g_bh [C_DIM * N_DIM];
__device__ __align__(128) bf16  g_bl [C_DIM * N_DIM];
__device__ __align__(128) bf16  g_ch [C_DIM * N_DIM];
__device__ __align__(128) bf16  g_cl [C_DIM * N_DIM];
// per-channel conv weights: [n][k=192][t=64]  (k<64: Toeplitz rows, k>=64: basis)
__device__ __align__(128) bf16  g_wbh[(size_t)N_DIM * 192 * 64];
__device__ __align__(128) bf16  g_wbl[(size_t)N_DIM * 192 * 64];
// per-channel contribution weights: [n][i=64][mode=128]
__device__ __align__(128) bf16  g_wch[(size_t)N_DIM * 64 * 128];
__device__ __align__(128) bf16  g_wcl[(size_t)N_DIM * 64 * 128];
// chunk contributions: [chain][chunk=128][mode=128] fp32
__device__ __align__(128) float g_c  [(size_t)B_SZ * N_DIM * NCHK * 128];
// chunk-boundary states (h_pre, split): [chain][chunk=128][mode=128]
__device__ __align__(128) bf16  g_hh [(size_t)B_SZ * N_DIM * NCHK * 128];
__device__ __align__(128) bf16  g_hl [(size_t)B_SZ * N_DIM * NCHK * 128];

// ---------------------------------------------------------------------------
// Helpers (base PTX only)
// ---------------------------------------------------------------------------
__device__ __forceinline__ uint32_t smem_u32(const void* p) {
    uint32_t a;
    asm("{ .reg .u64 t; cvta.to.shared.u64 t, %1; cvt.u32.u64 %0, t; }" : "=r"(a) : "l"(p));
    return a;
}
__device__ __forceinline__ void cpa16(uint32_t d, const void* s) {
    asm volatile("cp.async.cg.shared.global [%0], [%1], 16;" :: "r"(d), "l"(s));
}
#define CP_COMMIT() asm volatile("cp.async.commit_group;" ::: "memory")
#define CP_WAIT2()  asm volatile("cp.async.wait_group 2;"  ::: "memory")

#define LDSM_X4(r0,r1,r2,r3,addr) \
    asm volatile("ldmatrix.sync.aligned.m8n8.x4.shared.b16 {%0,%1,%2,%3}, [%4];" \
        : "=r"(r0), "=r"(r1), "=r"(r2), "=r"(r3) : "r"(addr))
#define LDSM_X4T(r0,r1,r2,r3,addr) \
    asm volatile("ldmatrix.sync.aligned.m8n8.x4.trans.shared.b16 {%0,%1,%2,%3}, [%4];" \
        : "=r"(r0), "=r"(r1), "=r"(r2), "=r"(r3) : "r"(addr))

#define MMA16816(d, a, b0v, b1v) \
    asm volatile("mma.sync.aligned.m16n8k16.row.col.f32.bf16.bf16.f32 " \
        "{%0,%1,%2,%3}, {%4,%5,%6,%7}, {%8,%9}, {%0,%1,%2,%3};" \
        : "+f"((d)[0]), "+f"((d)[1]), "+f"((d)[2]), "+f"((d)[3]) \
        : "r"((a)[0]), "r"((a)[1]), "r"((a)[2]), "r"((a)[3]), "r"(b0v), "r"(b1v))

__device__ __forceinline__ void split1(float v, bf16& h, bf16& l) {
    h = __float2bfloat16_rn(v);
    l = __float2bfloat16_rn(v - __bfloat162float(h));
}

// ---------------------------------------------------------------------------
// fp32 -> bf16 hi/lo split (pre-pass)
// ---------------------------------------------------------------------------
__global__ __launch_bounds__(256) void split_fp32(
    const float* __restrict__ src, bf16* __restrict__ hi, bf16* __restrict__ lo, int n)
{
    int i = (blockIdx.x * 256 + threadIdx.x) * 4;
    if (i >= n) return;
    float4 v = *(const float4*)(src + i);
    bf16 h0, l0, h1, l1, h2, l2, h3, l3;
    split1(v.x, h0, l0); split1(v.y, h1, l1);
    split1(v.z, h2, l2); split1(v.w, h3, l3);
    ((__nv_bfloat162*)(hi + i))[0] = __nv_bfloat162(h0, h1);
    ((__nv_bfloat162*)(hi + i))[1] = __nv_bfloat162(h2, h3);
    ((__nv_bfloat162*)(lo + i))[0] = __nv_bfloat162(l0, l1);
    ((__nv_bfloat162*)(lo + i))[1] = __nv_bfloat162(l2, l3);
}

// ---------------------------------------------------------------------------
// HMMA GEMM: Out[b] = W(512x512) @ X[b](512x8192), fp32 via 3-term bf16 split.
// If OutF != nullptr -> fp32 out, else split bf16 out to OutH/OutL.
// ---------------------------------------------------------------------------
#define STAGE   18432
#define A_BYTES 10240
#define NCHUNK  48
#define GEMM_SMEM (4 * STAGE)

__global__ __launch_bounds__(256, 2) void hgemm(
    const bf16* __restrict__ Ah, const bf16* __restrict__ Al,
    const bf16* __restrict__ Bh0, const bf16* __restrict__ Bl0,
    float* __restrict__ OutF, bf16* __restrict__ OutH, bf16* __restrict__ OutL)
{
    extern __shared__ char smem[];
    const uint32_t sb = smem_u32(smem);
    const int tid  = threadIdx.x;
    const int lane = tid & 31, wid = tid >> 5;
    const int n0 = blockIdx.x * 128;
    const int m0 = blockIdx.y * 128;
    const size_t boff = (size_t)blockIdx.z * C_DIM * L_DIM;
    const bf16* Bh = Bh0 + boff;
    const bf16* Bl = Bl0 + boff;

    const int am = tid >> 2, ac = tid & 3;
    const int bk = tid >> 4, bc = tid & 15;

    auto load_stage = [&](int cl, int st) {
        if (cl < NCHUNK) {
            const bf16* As = (cl < 32) ? Ah : Al;
            const bf16* Bs = (cl >= 16 && cl < 32) ? Bl : Bh;
            const int k0 = (cl & 15) << 5;
            const uint32_t s0 = sb + (uint32_t)st * STAGE;
            cpa16(s0 + am * 80 + ac * 16,
                  As + (size_t)(m0 + am) * C_DIM + k0 + ac * 8);
            cpa16(s0 + (am + 64) * 80 + ac * 16,
                  As + (size_t)(m0 + am + 64) * C_DIM + k0 + ac * 8);
            {
                int c1 = (bc & 8) | ((bc ^ (bk & 7)) & 7);
                cpa16(s0 + A_BYTES + bk * 256 + c1 * 16,
                      Bs + (size_t)(k0 + bk) * L_DIM + n0 + bc * 8);
                int k2 = bk + 16;
                int c2 = (bc & 8) | ((bc ^ (k2 & 7)) & 7);
                cpa16(s0 + A_BYTES + k2 * 256 + c2 * 16,
                      Bs + (size_t)(k0 + k2) * L_DIM + n0 + bc * 8);
            }
        }
        CP_COMMIT();
    };

    const int wm = (wid >> 2) * 64;
    const int wn = (wid & 3) * 32;
    const uint32_t a_base = (uint32_t)(wm + (lane & 15)) * 80 + ((lane >> 4) * 16);
    uint32_t b_off[2];
#pragma unroll
    for (int nt = 0; nt < 2; nt++) {
        int g  = (wn >> 3) + nt * 2 + (lane >> 4);
        int gp = (g & 8) | ((g ^ (lane & 7)) & 7);
        b_off[nt] = (uint32_t)(lane & 15) * 256 + gp * 16;
    }

    float acc[4][4][4];
#pragma unroll
    for (int mt = 0; mt < 4; mt++)
#pragma unroll
        for (int j = 0; j < 4; j++)
#pragma unroll
            for (int r = 0; r < 4; r++) acc[mt][j][r] = 0.f;

    load_stage(0, 0); load_stage(1, 1); load_stage(2, 2);

    for (int c = 0; c < NCHUNK; c++) {
        CP_WAIT2();
        __syncthreads();
        load_stage(c + 3, (c + 3) & 3);

        const uint32_t Abase = sb + (uint32_t)(c & 3) * STAGE;
        const uint32_t Bbase = Abase + A_BYTES;
#pragma unroll
        for (int kh = 0; kh < 2; kh++) {
            uint32_t a[4][4], b[2][4];
#pragma unroll
            for (int mt = 0; mt < 4; mt++)
                LDSM_X4(a[mt][0], a[mt][1], a[mt][2], a[mt][3],
                        Abase + a_base + mt * (16 * 80) + kh * 32);
#pragma unroll
            for (int nt = 0; nt < 2; nt++)
                LDSM_X4T(b[nt][0], b[nt][1], b[nt][2], b[nt][3],
                         Bbase + b_off[nt] + kh * 4096);
#pragma unroll
            for (int mt = 0; mt < 4; mt++) {
                MMA16816(acc[mt][0], a[mt], b[0][0], b[0][1]);
                MMA16816(acc[mt][1], a[mt], b[0][2], b[0][3]);
                MMA16816(acc[mt][2], a[mt], b[1][0], b[1][1]);
                MMA16816(acc[mt][3], a[mt], b[1][2], b[1][3]);
            }
        }
    }

    const int er = lane >> 2, ec = (lane & 3) * 2;
    const size_t outz = (size_t)blockIdx.z * N_DIM * L_DIM;
#pragma unroll
    for (int mt = 0; mt < 4; mt++) {
#pragma unroll
        for (int j = 0; j < 4; j++) {
            size_t base = outz + (size_t)(m0 + wm + mt * 16 + er) * L_DIM + (n0 + wn + j * 8 + ec);
            if (OutF) {
                *(float2*)&OutF[base]             = make_float2(acc[mt][j][0], acc[mt][j][1]);
                *(float2*)&OutF[base + 8 * L_DIM] = make_float2(acc[mt][j][2], acc[mt][j][3]);
            } else {
                bf16 h0, l0, h1, l1;
                split1(acc[mt][j][0], h0, l0); split1(acc[mt][j][1], h1, l1);
                *(__nv_bfloat162*)&OutH[base] = __nv_bfloat162(h0, h1);
                *(__nv_bfloat162*)&OutL[base] = __nv_bfloat162(l0, l1);
                split1(acc[mt][j][2], h0, l0); split1(acc[mt][j][3], h1, l1);
                *(__nv_bfloat162*)&OutH[base + 8 * L_DIM] = __nv_bfloat162(h0, h1);
                *(__nv_bfloat162*)&OutL[base + 8 * L_DIM] = __nv_bfloat162(l0, l1);
            }
        }
    }
}

// ---------------------------------------------------------------------------
// Prep (parallel, closed-form): per channel n build
//   Wc^T[i][2s]=Re(lam^{63-i}), [2s+1]=Im(lam^{63-i})              (contrib)
//   Wb[k<64][t]  = K[t-k] (t>=k) Toeplitz rows,  K[d]=Sum_s E Re(lam^d)
//   Wb[64+2s][t] = E Re(lam^{t+1}),  Wb[65+2s][t] = -E Im(lam^{t+1})
// lam^d computed directly: exp(d*a)*(cos(d*w), sin(d*w)). Staged in smem,
// coalesced copy-out with bf16 split. 256 threads: s=tid&63, dgroup=tid>>6.
// ---------------------------------------------------------------------------
#define PW_WB_OFF 0                         // sWb: 192 rows x 65 floats
#define PW_WC_OFF (192 * 65)                // sWc: 64*128 floats
#define PW_P_OFF  (PW_WC_OFF + 64 * 128)    // sP: 64 x 65 floats
#define PW_K_OFF  (PW_P_OFF + 64 * 65)      // sK: 64 floats
#define PW_SMEM   ((PW_K_OFF + 64) * 4)

__global__ __launch_bounds__(256) void prep_weights(
    const float* __restrict__ Ar, const float* __restrict__ Ai,
    const float* __restrict__ Ew,
    bf16* __restrict__ wbh, bf16* __restrict__ wbl,
    bf16* __restrict__ wch, bf16* __restrict__ wcl)
{
    extern __shared__ float sm[];
    float* sWb = sm + PW_WB_OFF;
    float* sWc = sm + PW_WC_OFF;
    float* sP  = sm + PW_P_OFF;
    float* sK  = sm + PW_K_OFF;

    const int n = blockIdx.x;
    const int tid = threadIdx.x;
    const int s = tid & 63;
    const int dg = tid >> 6;      // 0..3

    const float a = Ar[n * 64 + s], w = Ai[n * 64 + s], E = Ew[n * 64 + s];
    const float er = expf(a);
    const float lr = er * cosf(w), li = er * sinf(w);

#pragma unroll
    for (int dd = 0; dd < 16; dd++) {
        const int d = dg * 16 + dd;
        const float fd = (float)d;
        const float p  = expf(fd * a);
        const float cr = p * cosf(fd * w);
        const float ci = p * sinf(fd * w);
        // Wc row i = 63-d
        sWc[(63 - d) * 128 + 2 * s]     = cr;
        sWc[(63 - d) * 128 + 2 * s + 1] = ci;
        // K partials
        sP[d * 65 + s] = E * cr;
        // basis at t = d uses lam^{d+1}
        const float cr1 = cr * lr - ci * li;
        const float ci1 = cr * li + ci * lr;
        sWb[(64 + 2 * s) * 65 + d] = E * cr1;
        sWb[(65 + 2 * s) * 65 + d] = -E * ci1;
    }
    __syncthreads();
    if (tid < 64) {
        float acc = 0.f;
#pragma unroll
        for (int q = 0; q < 64; q++) acc += sP[tid * 65 + q];
        sK[tid] = acc;
    }
    __syncthreads();
    // Toeplitz rows k<64
    for (int i = tid; i < 64 * 64; i += 256) {
        int k = i >> 6, t = i & 63;
        sWb[k * 65 + t] = (t >= k) ? sK[t - k] : 0.f;
    }
    __syncthreads();
    // coalesced copy-out with split
    {
        bf16* dh = wbh + (size_t)n * 192 * 64;
        bf16* dl = wbl + (size_t)n * 192 * 64;
        for (int i = tid; i < 192 * 64; i += 256) {
            int r = i >> 6, t = i & 63;
            bf16 h, l; split1(sWb[r * 65 + t], h, l);
            dh[i] = h; dl[i] = l;
        }
    }
    {
        bf16* dh = wch + (size_t)n * 64 * 128;
        bf16* dl = wcl + (size_t)n * 64 * 128;
        for (int i = tid; i < 64 * 128; i += 256) {
            bf16 h, l; split1(sWc[i], h, l);
            dh[i] = h; dl[i] = l;
        }
    }
}

// ---------------------------------------------------------------------------
// Contribution GEMM: per (batch, channel):
//   Cc[j][mode] = Sum_i x[chain][j*64+i] * Wc^T[i][mode]
// M=128 (chunks j), N=128 (modes), K=64 (3-term split -> 6 virtual chunks).
// ---------------------------------------------------------------------------
#define CN_CHUNK 6
__global__ __launch_bounds__(256, 2) void contrib_gemm(
    const bf16* __restrict__ Xh, const bf16* __restrict__ Xl,
    const bf16* __restrict__ Wh, const bf16* __restrict__ Wl,
    float* __restrict__ Cc)
{
    extern __shared__ char smem[];
    const uint32_t sb = smem_u32(smem);
    const int tid  = threadIdx.x;
    const int lane = tid & 31, wid = tid >> 5;
    const int bb = blockIdx.x;          // batch
    const int n  = blockIdx.y;          // channel
    const size_t chain = (size_t)bb * N_DIM + n;

    const int am = tid >> 2, ac = tid & 3;
    const int bk = tid >> 4, bc = tid & 15;

    auto load_stage = [&](int cl, int st) {
        if (cl < CN_CHUNK) {
            const bf16* As = (cl < 4) ? Xh : Xl;
            const bf16* Bs = (cl >= 2 && cl < 4) ? Wl : Wh;
            const int khalf = (cl & 1) * 32;
            const uint32_t s0 = sb + (uint32_t)st * STAGE;
            cpa16(s0 + am * 80 + ac * 16,
                  As + chain * L_DIM + (size_t)am * 64 + khalf + ac * 8);
            cpa16(s0 + (am + 64) * 80 + ac * 16,
                  As + chain * L_DIM + (size_t)(am + 64) * 64 + khalf + ac * 8);
            {
                int c1 = (bc & 8) | ((bc ^ (bk & 7)) & 7);
                cpa16(s0 + A_BYTES + bk * 256 + c1 * 16,
                      Bs + ((size_t)n * 64 + khalf + bk) * 128 + bc * 8);
                int k2 = bk + 16;
                int c2 = (bc & 8) | ((bc ^ (k2 & 7)) & 7);
                cpa16(s0 + A_BYTES + k2 * 256 + c2 * 16,
                      Bs + ((size_t)n * 64 + khalf + k2) * 128 + bc * 8);
            }
        }
        CP_COMMIT();
    };

    const int wm = (wid >> 2) * 64;
    const int wn = (wid & 3) * 32;
    const uint32_t a_base = (uint32_t)(wm + (lane & 15)) * 80 + ((lane >> 4) * 16);
    uint32_t b_off[2];
#pragma unroll
    for (int nt = 0; nt < 2; nt++) {
        int g  = (wn >> 3) + nt * 2 + (lane >> 4);
        int gp = (g & 8) | ((g ^ (lane & 7)) & 7);
        b_off[nt] = (uint32_t)(lane & 15) * 256 + gp * 16;
    }

    float acc[4][4][4];
#pragma unroll
    for (int mt = 0; mt < 4; mt++)
#pragma unroll
        for (int j = 0; j < 4; j++)
#pragma unroll
            for (int r = 0; r < 4; r++) acc[mt][j][r] = 0.f;

    load_stage(0, 0); load_stage(1, 1); load_stage(2, 2);

    for (int c = 0; c < CN_CHUNK; c++) {
        CP_WAIT2();
        __syncthreads();
        load_stage(c + 3, (c + 3) & 3);

        const uint32_t Abase = sb + (uint32_t)(c & 3) * STAGE;
        const uint32_t Bbase = Abase + A_BYTES;
#pragma unroll
        for (int kh = 0; kh < 2; kh++) {
            uint32_t a[4][4], b[2][4];
#pragma unroll
            for (int mt = 0; mt < 4; mt++)
                LDSM_X4(a[mt][0], a[mt][1], a[mt][2], a[mt][3],
                        Abase + a_base + mt * (16 * 80) + kh * 32);
#pragma unroll
            for (int nt = 0; nt < 2; nt++)
                LDSM_X4T(b[nt][0], b[nt][1], b[nt][2], b[nt][3],
                         Bbase + b_off[nt] + kh * 4096);
#pragma unroll
            for (int mt = 0; mt < 4; mt++) {
                MMA16816(acc[mt][0], a[mt], b[0][0], b[0][1]);
                MMA16816(acc[mt][1], a[mt], b[0][2], b[0][3]);
                MMA16816(acc[mt][2], a[mt], b[1][0], b[1][1]);
                MMA16816(acc[mt][3], a[mt], b[1][2], b[1][3]);
            }
        }
    }

    const int er = lane >> 2, ec = (lane & 3) * 2;
    float* Cp = Cc + chain * NCHK * 128;
#pragma unroll
    for (int mt = 0; mt < 4; mt++) {
#pragma unroll
        for (int j = 0; j < 4; j++) {
            size_t base = (size_t)(wm + mt * 16 + er) * 128 + (wn + j * 8 + ec);
            *(float2*)&Cp[base]           = make_float2(acc[mt][j][0], acc[mt][j][1]);
            *(float2*)&Cp[base + 8 * 128] = make_float2(acc[mt][j][2], acc[mt][j][3]);
        }
    }
}

// ---------------------------------------------------------------------------
// Chunk state scan (tiny sequential): per chain, 128 chunk steps.
//   Hpre[j] = H;  H = Lam64 (.) H + Cc[j]
// ---------------------------------------------------------------------------
__global__ __launch_bounds__(128) void chunk_scan(
    const float* __restrict__ Cc, bf16* __restrict__ Hh, bf16* __restrict__ Hl,
    const float* __restrict__ Ar, const float* __restrict__ Ai)
{
    const int lane = threadIdx.x;
    const int w = threadIdx.y;
    const size_t chain = (size_t)blockIdx.x * 4 + w;
    const int n = (int)(chain & (N_DIM - 1));

    const int s0 = n * S_DIM + lane * 2;
    float2 av = *(const float2*)&Ar[s0];
    float2 wv = *(const float2*)&Ai[s0];
    const float p0 = expf(64.f * av.x), p1 = expf(64.f * av.y);
    const float g0 = 64.f * wv.x,       g1 = 64.f * wv.y;
    const float c640 = p0 * cosf(g0), s640 = p0 * sinf(g0);
    const float c641 = p1 * cosf(g1), s641 = p1 * sinf(g1);

    float hr0 = 0.f, hi0 = 0.f, hr1 = 0.f, hi1 = 0.f;
    const float* cp = Cc + chain * NCHK * 128;
    bf16* hhp = Hh + chain * NCHK * 128;
    bf16* hlp = Hl + chain * NCHK * 128;

    for (int j = 0; j < NCHK; j++) {
        bf16 a0, b0, a1, b1, a2, b2, a3, b3;
        split1(hr0, a0, b0); split1(hi0, a1, b1);
        split1(hr1, a2, b2); split1(hi1, a3, b3);
        size_t o = (size_t)j * 128 + lane * 4;
        *(__nv_bfloat162*)&hhp[o]     = __nv_bfloat162(a0, a1);
        *(__nv_bfloat162*)&hhp[o + 2] = __nv_bfloat162(a2, a3);
        *(__nv_bfloat162*)&hlp[o]     = __nv_bfloat162(b0, b1);
        *(__nv_bfloat162*)&hlp[o + 2] = __nv_bfloat162(b2, b3);
        float4 cv = *(const float4*)&cp[(size_t)j * 128 + lane * 4];
        float nr0 = c640 * hr0 - s640 * hi0 + cv.x;
        float ni0 = c640 * hi0 + s640 * hr0 + cv.y;
        float nr1 = c641 * hr1 - s641 * hi1 + cv.z;
        float ni1 = c641 * hi1 + s641 * hr1 + cv.w;
        hr0 = nr0; hi0 = ni0; hr1 = nr1; hi1 = ni1;
    }
}

// ---------------------------------------------------------------------------
// Conv GEMM: per (batch, channel):
//   y[j][t] = Sum_{k<64} x_j[k] K[t-k]  +  Sum_modes Hpre[j][m] Basis[m][t]
// M=128 (chunks j), N=64 (t), K=192 (3-term split -> 18 virtual chunks of 32).
// ---------------------------------------------------------------------------
#define VB_BYTES 4096
#define VSTAGE   (A_BYTES + VB_BYTES)      // 14336
#define VN_CHUNK 18
#define CONV_SMEM (4 * VSTAGE)

__global__ __launch_bounds__(256, 2) void conv_gemm(
    const bf16* __restrict__ Xh, const bf16* __restrict__ Xl,
    const bf16* __restrict__ Hh, const bf16* __restrict__ Hl,
    const bf16* __restrict__ Wh, const bf16* __restrict__ Wl,
    bf16* __restrict__ Yh, bf16* __restrict__ Yl)
{
    extern __shared__ char smem[];
    const uint32_t sb = smem_u32(smem);
    const int tid  = threadIdx.x;
    const int lane = tid & 31, wid = tid >> 5;
    const int bb = blockIdx.x;
    const int n  = blockIdx.y;
    const size_t chain = (size_t)bb * N_DIM + n;

    const int am = tid >> 2, ac = tid & 3;
    const int vk = tid >> 3, vc = tid & 7;      // B loader: 32 rows x 8 chunks

    auto load_stage = [&](int cl, int st) {
        if (cl < VN_CHUNK) {
            const int term = cl / 6, kc = cl % 6;
            const uint32_t s0 = sb + (uint32_t)st * VSTAGE;
            const bf16* rowsrc;
            size_t rstride, roff;
            if (kc < 2) {
                rowsrc = (term < 2) ? Xh : Xl;
                rowsrc += chain * L_DIM;
                rstride = 64; roff = (size_t)kc * 32;
            } else {
                rowsrc = (term < 2) ? Hh : Hl;
                rowsrc += chain * NCHK * 128;
                rstride = 128; roff = (size_t)(kc - 2) * 32;
            }
            cpa16(s0 + am * 80 + ac * 16,
                  rowsrc + (size_t)am * rstride + roff + ac * 8);
            cpa16(s0 + (am + 64) * 80 + ac * 16,
                  rowsrc + (size_t)(am + 64) * rstride + roff + ac * 8);
            const bf16* Bs = (term == 1) ? Wl : Wh;
            int cp = vc ^ (vk & 7);
            cpa16(s0 + A_BYTES + vk * 128 + cp * 16,
                  Bs + ((size_t)n * 192 + (size_t)kc * 32 + vk) * 64 + vc * 8);
        }
        CP_COMMIT();
    };

    const int wm = (wid >> 2) * 64;      // M: 2 groups of 64
    const int wn = (wid & 3) * 16;       // N: 4 groups of 16
    const uint32_t a_base = (uint32_t)(wm + (lane & 15)) * 80 + ((lane >> 4) * 16);

    float acc[4][2][4];
#pragma unroll
    for (int mt = 0; mt < 4; mt++)
#pragma unroll
        for (int j = 0; j < 2; j++)
#pragma unroll
            for (int r = 0; r < 4; r++) acc[mt][j][r] = 0.f;

    load_stage(0, 0); load_stage(1, 1); load_stage(2, 2);

    for (int c = 0; c < VN_CHUNK; c++) {
        CP_WAIT2();
        __syncthreads();
        load_stage(c + 3, (c + 3) & 3);

        const uint32_t Abase = sb + (uint32_t)(c & 3) * VSTAGE;
        const uint32_t Bbase = Abase + A_BYTES;
#pragma unroll
        for (int kh = 0; kh < 2; kh++) {
            uint32_t a[4][4], b[4];
#pragma unroll
            for (int mt = 0; mt < 4; mt++)
                LDSM_X4(a[mt][0], a[mt][1], a[mt][2], a[mt][3],
                        Abase + a_base + mt * (16 * 80) + kh * 32);
            {
                int krow = kh * 16 + (lane & 15);
                int g = (wn >> 3) + (lane >> 4);
                uint32_t boff = (uint32_t)krow * 128 + (uint32_t)(((g ^ (krow & 7)) & 7) * 16);
                LDSM_X4T(b[0], b[1], b[2], b[3], Bbase + boff);
            }
#pragma unroll
            for (int mt = 0; mt < 4; mt++) {
                MMA16816(acc[mt][0], a[mt], b[0], b[1]);
                MMA16816(acc[mt][1], a[mt], b[2], b[3]);
            }
        }
    }

    const int er = lane >> 2, ec = (lane & 3) * 2;
    bf16* yhp = Yh + chain * L_DIM;
    bf16* ylp = Yl + chain * L_DIM;
#pragma unroll
    for (int mt = 0; mt < 4; mt++) {
#pragma unroll
        for (int j = 0; j < 2; j++) {
            int row0 = wm + mt * 16 + er;        // chunk index j
            int tcol = wn + j * 8 + ec;
            size_t b0 = (size_t)row0 * 64 + tcol;
            bf16 h0, l0, h1, l1;
            split1(acc[mt][j][0], h0, l0); split1(acc[mt][j][1], h1, l1);
            *(__nv_bfloat162*)&yhp[b0] = __nv_bfloat162(h0, h1);
            *(__nv_bfloat162*)&ylp[b0] = __nv_bfloat162(l0, l1);
            size_t b1 = (size_t)(row0 + 8) * 64 + tcol;
            split1(acc[mt][j][2], h0, l0); split1(acc[mt][j][3], h1, l1);
            *(__nv_bfloat162*)&yhp[b1] = __nv_bfloat162(h0, h1);
            *(__nv_bfloat162*)&ylp[b1] = __nv_bfloat162(l0, l1);
        }
    }
}

// ---------------------------------------------------------------------------
extern "C" void kernel_launch(void* const* d_in, const int* in_sizes, int n_in,
                              void* d_out, int out_size)
{
    const float* inp = (const float*)d_in[0];  // [B, C, L]
    const float* ar  = (const float*)d_in[1];  // [N, S]
    const float* ai  = (const float*)d_in[2];  // [N, S]
    const float* Bm  = (const float*)d_in[3];  // [N, C]
    const float* Cm  = (const float*)d_in[4];  // [C, N]
    const float* E   = (const float*)d_in[5];  // [N, S]
    float* out = (float*)d_out;                // [B, C, L]

    bf16 *inh, *inl, *xh, *xl, *yh, *yl, *bh, *bl, *ch, *cl;
    bf16 *wbh, *wbl, *wch, *wcl, *hh, *hl;
    float *cc;
    cudaGetSymbolAddress((void**)&inh, g_inh);
    cudaGetSymbolAddress((void**)&inl, g_inl);
    cudaGetSymbolAddress((void**)&xh,  g_xh);
    cudaGetSymbolAddress((void**)&xl,  g_xl);
    cudaGetSymbolAddress((void**)&yh,  g_yh);
    cudaGetSymbolAddress((void**)&yl,  g_yl);
    cudaGetSymbolAddress((void**)&bh,  g_bh);
    cudaGetSymbolAddress((void**)&bl,  g_bl);
    cudaGetSymbolAddress((void**)&ch,  g_ch);
    cudaGetSymbolAddress((void**)&cl,  g_cl);
    cudaGetSymbolAddress((void**)&wbh, g_wbh);
    cudaGetSymbolAddress((void**)&wbl, g_wbl);
    cudaGetSymbolAddress((void**)&wch, g_wch);
    cudaGetSymbolAddress((void**)&wcl, g_wcl);
    cudaGetSymbolAddress((void**)&hh,  g_hh);
    cudaGetSymbolAddress((void**)&hl,  g_hl);
    cudaGetSymbolAddress((void**)&cc,  g_c);

    cudaFuncSetAttribute(hgemm,        cudaFuncAttributeMaxDynamicSharedMemorySize, GEMM_SMEM);
    cudaFuncSetAttribute(contrib_gemm, cudaFuncAttributeMaxDynamicSharedMemorySize, GEMM_SMEM);
    cudaFuncSetAttribute(conv_gemm,    cudaFuncAttributeMaxDynamicSharedMemorySize, CONV_SMEM);
    cudaFuncSetAttribute(prep_weights, cudaFuncAttributeMaxDynamicSharedMemorySize, PW_SMEM);

    const int n_in_elems = B_SZ * C_DIM * L_DIM;
    const int n_w = C_DIM * N_DIM;

    split_fp32<<<n_in_elems / 1024, 256>>>(inp, inh, inl, n_in_elems);
    split_fp32<<<n_w / 1024, 256>>>(Bm, bh, bl, n_w);
    split_fp32<<<n_w / 1024, 256>>>(Cm, ch, cl, n_w);
    prep_weights<<<N_DIM, 256, PW_SMEM>>>(ar, ai, E, wbh, wbl, wch, wcl);

    dim3 gg(L_DIM / 128, N_DIM / 128, B_SZ);
    hgemm<<<gg, 256, GEMM_SMEM>>>(bh, bl, inh, inl, nullptr, xh, xl);   // x = B@input (split out)

    contrib_gemm<<<dim3(B_SZ, N_DIM), 256, GEMM_SMEM>>>(xh, xl, wch, wcl, cc);
    chunk_scan<<<(B_SZ * N_DIM) / 4, dim3(32, 4)>>>(cc, hh, hl, ar, ai);
    conv_gemm<<<dim3(B_SZ, N_DIM), 256, CONV_SMEM>>>(xh, xl, hh, hl, wbh, wbl, yh, yl);

    hgemm<<<gg, 256, GEMM_SMEM>>>(ch, cl, yh, yl, out, nullptr, nullptr); // out = C@y
}

// round 8
// speedup vs baseline: 1.6445x; 1.0196x over previous
#include <cuda_runtime.h>
#include <cuda_bf16.h>
#include <cstdint>
#include <math.h>

#define B_SZ   4
#define C_DIM  512
#define N_DIM  512
#define S_DIM  64
#define L_DIM  8192
#define NCHK   128

typedef __nv_bfloat16 bf16;

// ---------------------------------------------------------------------------
// Scratch (allocation-free rule: __device__ globals)
// ---------------------------------------------------------------------------
__device__ __align__(128) bf16  g_inh[(size_t)B_SZ * C_DIM * L_DIM];
__device__ __align__(128) bf16  g_inl[(size_t)B_SZ * C_DIM * L_DIM];
__device__ __align__(128) bf16  g_xh [(size_t)B_SZ * N_DIM * L_DIM];
__device__ __align__(128) bf16  g_xl [(size_t)B_SZ * N_DIM * L_DIM];
__device__ __align__(128) bf16  g_yh [(size_t)B_SZ * N_DIM * L_DIM];
__device__ __align__(128) bf16  g_yl [(size_t)B_SZ * N_DIM * L_DIM];
__device__ __align__(128) bf16  g_bh [C_DIM * N_DIM];
__device__ __align__(128) bf16  g_bl [C_DIM * N_DIM];
__device__ __align__(128) bf16  g_ch [C_DIM * N_DIM];
__device__ __align__(128) bf16  g_cl [C_DIM * N_DIM];
__device__ __align__(128) bf16  g_wbh[(size_t)N_DIM * 192 * 64];
__device__ __align__(128) bf16  g_wbl[(size_t)N_DIM * 192 * 64];
__device__ __align__(128) bf16  g_wch[(size_t)N_DIM * 64 * 128];
__device__ __align__(128) bf16  g_wcl[(size_t)N_DIM * 64 * 128];

// ---------------------------------------------------------------------------
// Helpers (base PTX only)
// ---------------------------------------------------------------------------
__device__ __forceinline__ uint32_t smem_u32(const void* p) {
    uint32_t a;
    asm("{ .reg .u64 t; cvta.to.shared.u64 t, %1; cvt.u32.u64 %0, t; }" : "=r"(a) : "l"(p));
    return a;
}
__device__ __forceinline__ void cpa16(uint32_t d, const void* s) {
    asm volatile("cp.async.cg.shared.global [%0], [%1], 16;" :: "r"(d), "l"(s));
}
#define CP_COMMIT()  asm volatile("cp.async.commit_group;" ::: "memory")
#define CP_WAIT2()   asm volatile("cp.async.wait_group 2;"  ::: "memory")
#define CP_WAIT_ALL() asm volatile("cp.async.wait_group 0;" ::: "memory")

#define LDSM_X4(r0,r1,r2,r3,addr) \
    asm volatile("ldmatrix.sync.aligned.m8n8.x4.shared.b16 {%0,%1,%2,%3}, [%4];" \
        : "=r"(r0), "=r"(r1), "=r"(r2), "=r"(r3) : "r"(addr))
#define LDSM_X4T(r0,r1,r2,r3,addr) \
    asm volatile("ldmatrix.sync.aligned.m8n8.x4.trans.shared.b16 {%0,%1,%2,%3}, [%4];" \
        : "=r"(r0), "=r"(r1), "=r"(r2), "=r"(r3) : "r"(addr))

#define MMA16816(d, a, b0v, b1v) \
    asm volatile("mma.sync.aligned.m16n8k16.row.col.f32.bf16.bf16.f32 " \
        "{%0,%1,%2,%3}, {%4,%5,%6,%7}, {%8,%9}, {%0,%1,%2,%3};" \
        : "+f"((d)[0]), "+f"((d)[1]), "+f"((d)[2]), "+f"((d)[3]) \
        : "r"((a)[0]), "r"((a)[1]), "r"((a)[2]), "r"((a)[3]), "r"(b0v), "r"(b1v))

__device__ __forceinline__ void split1(float v, bf16& h, bf16& l) {
    h = __float2bfloat16_rn(v);
    l = __float2bfloat16_rn(v - __bfloat162float(h));
}

// ---------------------------------------------------------------------------
// fp32 -> bf16 hi/lo split (pre-pass)
// ---------------------------------------------------------------------------
__global__ __launch_bounds__(256) void split_fp32(
    const float* __restrict__ src, bf16* __restrict__ hi, bf16* __restrict__ lo, int n)
{
    int i = (blockIdx.x * 256 + threadIdx.x) * 4;
    if (i >= n) return;
    float4 v = *(const float4*)(src + i);
    bf16 h0, l0, h1, l1, h2, l2, h3, l3;
    split1(v.x, h0, l0); split1(v.y, h1, l1);
    split1(v.z, h2, l2); split1(v.w, h3, l3);
    ((__nv_bfloat162*)(hi + i))[0] = __nv_bfloat162(h0, h1);
    ((__nv_bfloat162*)(hi + i))[1] = __nv_bfloat162(h2, h3);
    ((__nv_bfloat162*)(lo + i))[0] = __nv_bfloat162(l0, l1);
    ((__nv_bfloat162*)(lo + i))[1] = __nv_bfloat162(l2, l3);
}

// ---------------------------------------------------------------------------
// HMMA GEMM (proven 142us): Out[b] = W(512x512) @ X[b](512x8192)
// ---------------------------------------------------------------------------
#define STAGE   18432
#define A_BYTES 10240
#define NCHUNK  48
#define GEMM_SMEM (4 * STAGE)

__global__ __launch_bounds__(256, 2) void hgemm(
    const bf16* __restrict__ Ah, const bf16* __restrict__ Al,
    const bf16* __restrict__ Bh0, const bf16* __restrict__ Bl0,
    float* __restrict__ OutF, bf16* __restrict__ OutH, bf16* __restrict__ OutL)
{
    extern __shared__ char smem[];
    const uint32_t sb = smem_u32(smem);
    const int tid  = threadIdx.x;
    const int lane = tid & 31, wid = tid >> 5;
    const int n0 = blockIdx.x * 128;
    const int m0 = blockIdx.y * 128;
    const size_t boff = (size_t)blockIdx.z * C_DIM * L_DIM;
    const bf16* Bh = Bh0 + boff;
    const bf16* Bl = Bl0 + boff;

    const int am = tid >> 2, ac = tid & 3;
    const int bk = tid >> 4, bc = tid & 15;

    auto load_stage = [&](int cl, int st) {
        if (cl < NCHUNK) {
            const bf16* As = (cl < 32) ? Ah : Al;
            const bf16* Bs = (cl >= 16 && cl < 32) ? Bl : Bh;
            const int k0 = (cl & 15) << 5;
            const uint32_t s0 = sb + (uint32_t)st * STAGE;
            cpa16(s0 + am * 80 + ac * 16,
                  As + (size_t)(m0 + am) * C_DIM + k0 + ac * 8);
            cpa16(s0 + (am + 64) * 80 + ac * 16,
                  As + (size_t)(m0 + am + 64) * C_DIM + k0 + ac * 8);
            {
                int c1 = (bc & 8) | ((bc ^ (bk & 7)) & 7);
                cpa16(s0 + A_BYTES + bk * 256 + c1 * 16,
                      Bs + (size_t)(k0 + bk) * L_DIM + n0 + bc * 8);
                int k2 = bk + 16;
                int c2 = (bc & 8) | ((bc ^ (k2 & 7)) & 7);
                cpa16(s0 + A_BYTES + k2 * 256 + c2 * 16,
                      Bs + (size_t)(k0 + k2) * L_DIM + n0 + bc * 8);
            }
        }
        CP_COMMIT();
    };

    const int wm = (wid >> 2) * 64;
    const int wn = (wid & 3) * 32;
    const uint32_t a_base = (uint32_t)(wm + (lane & 15)) * 80 + ((lane >> 4) * 16);
    uint32_t b_off[2];
#pragma unroll
    for (int nt = 0; nt < 2; nt++) {
        int g  = (wn >> 3) + nt * 2 + (lane >> 4);
        int gp = (g & 8) | ((g ^ (lane & 7)) & 7);
        b_off[nt] = (uint32_t)(lane & 15) * 256 + gp * 16;
    }

    float acc[4][4][4];
#pragma unroll
    for (int mt = 0; mt < 4; mt++)
#pragma unroll
        for (int j = 0; j < 4; j++)
#pragma unroll
            for (int r = 0; r < 4; r++) acc[mt][j][r] = 0.f;

    load_stage(0, 0); load_stage(1, 1); load_stage(2, 2);

    for (int c = 0; c < NCHUNK; c++) {
        CP_WAIT2();
        __syncthreads();
        load_stage(c + 3, (c + 3) & 3);

        const uint32_t Abase = sb + (uint32_t)(c & 3) * STAGE;
        const uint32_t Bbase = Abase + A_BYTES;
#pragma unroll
        for (int kh = 0; kh < 2; kh++) {
            uint32_t a[4][4], b[2][4];
#pragma unroll
            for (int mt = 0; mt < 4; mt++)
                LDSM_X4(a[mt][0], a[mt][1], a[mt][2], a[mt][3],
                        Abase + a_base + mt * (16 * 80) + kh * 32);
#pragma unroll
            for (int nt = 0; nt < 2; nt++)
                LDSM_X4T(b[nt][0], b[nt][1], b[nt][2], b[nt][3],
                         Bbase + b_off[nt] + kh * 4096);
#pragma unroll
            for (int mt = 0; mt < 4; mt++) {
                MMA16816(acc[mt][0], a[mt], b[0][0], b[0][1]);
                MMA16816(acc[mt][1], a[mt], b[0][2], b[0][3]);
                MMA16816(acc[mt][2], a[mt], b[1][0], b[1][1]);
                MMA16816(acc[mt][3], a[mt], b[1][2], b[1][3]);
            }
        }
    }

    const int er = lane >> 2, ec = (lane & 3) * 2;
    const size_t outz = (size_t)blockIdx.z * N_DIM * L_DIM;
#pragma unroll
    for (int mt = 0; mt < 4; mt++) {
#pragma unroll
        for (int j = 0; j < 4; j++) {
            size_t base = outz + (size_t)(m0 + wm + mt * 16 + er) * L_DIM + (n0 + wn + j * 8 + ec);
            if (OutF) {
                *(float2*)&OutF[base]             = make_float2(acc[mt][j][0], acc[mt][j][1]);
                *(float2*)&OutF[base + 8 * L_DIM] = make_float2(acc[mt][j][2], acc[mt][j][3]);
            } else {
                bf16 h0, l0, h1, l1;
                split1(acc[mt][j][0], h0, l0); split1(acc[mt][j][1], h1, l1);
                *(__nv_bfloat162*)&OutH[base] = __nv_bfloat162(h0, h1);
                *(__nv_bfloat162*)&OutL[base] = __nv_bfloat162(l0, l1);
                split1(acc[mt][j][2], h0, l0); split1(acc[mt][j][3], h1, l1);
                *(__nv_bfloat162*)&OutH[base + 8 * L_DIM] = __nv_bfloat162(h0, h1);
                *(__nv_bfloat162*)&OutL[base + 8 * L_DIM] = __nv_bfloat162(l0, l1);
            }
        }
    }
}

// ---------------------------------------------------------------------------
// Prep (parallel, closed-form) — unchanged from R7 (20us)
// ---------------------------------------------------------------------------
#define PW_WB_OFF 0
#define PW_WC_OFF (192 * 65)
#define PW_P_OFF  (PW_WC_OFF + 64 * 128)
#define PW_K_OFF  (PW_P_OFF + 64 * 65)
#define PW_SMEM   ((PW_K_OFF + 64) * 4)

__global__ __launch_bounds__(256) void prep_weights(
    const float* __restrict__ Ar, const float* __restrict__ Ai,
    const float* __restrict__ Ew,
    bf16* __restrict__ wbh, bf16* __restrict__ wbl,
    bf16* __restrict__ wch, bf16* __restrict__ wcl)
{
    extern __shared__ float sm[];
    float* sWb = sm + PW_WB_OFF;
    float* sWc = sm + PW_WC_OFF;
    float* sP  = sm + PW_P_OFF;
    float* sK  = sm + PW_K_OFF;

    const int n = blockIdx.x;
    const int tid = threadIdx.x;
    const int s = tid & 63;
    const int dg = tid >> 6;

    const float a = Ar[n * 64 + s], w = Ai[n * 64 + s], E = Ew[n * 64 + s];
    const float er = expf(a);
    const float lr = er * cosf(w), li = er * sinf(w);

#pragma unroll
    for (int dd = 0; dd < 16; dd++) {
        const int d = dg * 16 + dd;
        const float fd = (float)d;
        const float p  = expf(fd * a);
        const float cr = p * cosf(fd * w);
        const float ci = p * sinf(fd * w);
        sWc[(63 - d) * 128 + 2 * s]     = cr;
        sWc[(63 - d) * 128 + 2 * s + 1] = ci;
        sP[d * 65 + s] = E * cr;
        const float cr1 = cr * lr - ci * li;
        const float ci1 = cr * li + ci * lr;
        sWb[(64 + 2 * s) * 65 + d] = E * cr1;
        sWb[(65 + 2 * s) * 65 + d] = -E * ci1;
    }
    __syncthreads();
    if (tid < 64) {
        float acc = 0.f;
#pragma unroll
        for (int q = 0; q < 64; q++) acc += sP[tid * 65 + q];
        sK[tid] = acc;
    }
    __syncthreads();
    for (int i = tid; i < 64 * 64; i += 256) {
        int k = i >> 6, t = i & 63;
        sWb[k * 65 + t] = (t >= k) ? sK[t - k] : 0.f;
    }
    __syncthreads();
    {
        bf16* dh = wbh + (size_t)n * 192 * 64;
        bf16* dl = wbl + (size_t)n * 192 * 64;
        for (int i = tid; i < 192 * 64; i += 256) {
            int r = i >> 6, t = i & 63;
            bf16 h, l; split1(sWb[r * 65 + t], h, l);
            dh[i] = h; dl[i] = l;
        }
    }
    {
        bf16* dh = wch + (size_t)n * 64 * 128;
        bf16* dl = wcl + (size_t)n * 64 * 128;
        for (int i = tid; i < 64 * 128; i += 256) {
            bf16 h, l; split1(sWc[i], h, l);
            dh[i] = h; dl[i] = l;
        }
    }
}

// ---------------------------------------------------------------------------
// FUSED middle kernel: per (batch, channel) CTA, 256 threads.
//   phase 1: Cc[j][m] = sum_i x[j*64+i] Wc[i][m]      (contrib MMAs)
//            -> written bf16-split into H panels (conv-A layout)
//   phase 2: in-block chunk scan, in-place Cc -> Hpre (panel slots)
//   phase 3: y[j][t] = sum_k<64 x_j[k] K[t-k] + sum_m Hpre[j][m] Basis[m][t]
// All operands resident in SMEM; no gmem intermediates.
// ---------------------------------------------------------------------------
#define FK_PANEL  10320                     // 128 rows x 80B + 80B pad (bank stagger)
#define FK_PX_OFF 0                         // 4 panels: xh k0-31, xh k32-63, xl k0-31, xl k32-63
#define FK_PH_OFF (4 * FK_PANEL)            // 8 panels: Hh m0-31..m96-127, then Hl x4
#define FK_WC_OFF (12 * FK_PANEL)           // Wc: h 16384 + l 16384 (256B rows, hgemm swizzle)
#define FK_WB_OFF (FK_WC_OFF + 32768)       // Wb: h 24576 + l 24576 (128B rows, conv swizzle)
#define FK_SMEM   (FK_WB_OFF + 49152)       // 205760 bytes

__global__ __launch_bounds__(256, 1) void fused_mid(
    const bf16* __restrict__ Xh, const bf16* __restrict__ Xl,
    const bf16* __restrict__ Wch, const bf16* __restrict__ Wcl,
    const bf16* __restrict__ Wbh, const bf16* __restrict__ Wbl,
    const float* __restrict__ Ar, const float* __restrict__ Ai,
    bf16* __restrict__ Yh, bf16* __restrict__ Yl)
{
    extern __shared__ char smem[];
    const uint32_t sb = smem_u32(smem);
    const int tid  = threadIdx.x;
    const int lane = tid & 31, wid = tid >> 5;
    const int bb = blockIdx.x;
    const int n  = blockIdx.y;
    const size_t chain = (size_t)bb * N_DIM + n;

    // ---- load everything (cp.async), one barrier -------------------------
    // x: per term 128 rows x 8 16B-chunks
    for (int t = 0; t < 2; t++) {
        const bf16* src = (t == 0) ? (Xh + chain * L_DIM) : (Xl + chain * L_DIM);
        for (int q = tid; q < 1024; q += 256) {
            int j = q >> 3, c = q & 7;
            uint32_t dst = sb + FK_PX_OFF + (uint32_t)(t * 2 + (c >> 2)) * FK_PANEL
                         + j * 80 + (c & 3) * 16;
            cpa16(dst, src + (size_t)j * 64 + c * 8);
        }
    }
    // Wc: per term 64 rows x 16 chunks, hgemm B swizzle
    for (int t = 0; t < 2; t++) {
        const bf16* src = ((t == 0) ? Wch : Wcl) + (size_t)n * 64 * 128;
        for (int q = tid; q < 1024; q += 256) {
            int r = q >> 4, c = q & 15;
            int cp = (c & 8) | ((c ^ (r & 7)) & 7);
            cpa16(sb + FK_WC_OFF + t * 16384 + r * 256 + cp * 16,
                  src + (size_t)r * 128 + c * 8);
        }
    }
    // Wb: per term 192 rows x 8 chunks, conv B swizzle
    for (int t = 0; t < 2; t++) {
        const bf16* src = ((t == 0) ? Wbh : Wbl) + (size_t)n * 192 * 64;
        for (int q = tid; q < 1536; q += 256) {
            int r = q >> 3, c = q & 7;
            int cp = c ^ (r & 7);
            cpa16(sb + FK_WB_OFF + t * 24576 + r * 128 + cp * 16,
                  src + (size_t)r * 64 + c * 8);
        }
    }
    CP_COMMIT();
    CP_WAIT_ALL();
    __syncthreads();

    // ---- phase 1: contrib MMAs ------------------------------------------
    const int wm = (wid >> 2) * 64;
    const int wn128 = (wid & 3) * 32;
    const uint32_t a_base = (uint32_t)(wm + (lane & 15)) * 80 + ((lane >> 4) * 16);
    uint32_t b_off[2];
#pragma unroll
    for (int nt = 0; nt < 2; nt++) {
        int g  = (wn128 >> 3) + nt * 2 + (lane >> 4);
        int gp = (g & 8) | ((g ^ (lane & 7)) & 7);
        b_off[nt] = (uint32_t)(lane & 15) * 256 + gp * 16;
    }

    {
        float acc[4][4][4];
#pragma unroll
        for (int mt = 0; mt < 4; mt++)
#pragma unroll
            for (int j = 0; j < 4; j++)
#pragma unroll
                for (int r = 0; r < 4; r++) acc[mt][j][r] = 0.f;

#pragma unroll
        for (int cl = 0; cl < 6; cl++) {
            // cl: 0(XhWh k0) 1(XhWh k32) 2(XhWl k0) 3(XhWl k32) 4(XlWh k0) 5(XlWh k32)
            const uint32_t Apan = sb + FK_PX_OFF + (uint32_t)(((cl < 4) ? 0 : 2) + (cl & 1)) * FK_PANEL;
            const uint32_t Bbase = sb + FK_WC_OFF + ((cl == 2 || cl == 3) ? 16384u : 0u)
                                 + (uint32_t)(cl & 1) * 0;  // khalf folded into panel choice below
            const uint32_t khalf256 = 0;  // Wc rows: need khalf offset
            (void)khalf256;
            const uint32_t Bk = sb + FK_WC_OFF + ((cl == 2 || cl == 3) ? 16384u : 0u)
                              + (uint32_t)((cl & 1) * 32) * 256;
            (void)Bbase;
#pragma unroll
            for (int kh = 0; kh < 2; kh++) {
                uint32_t a[4][4], b[2][4];
#pragma unroll
                for (int mt = 0; mt < 4; mt++)
                    LDSM_X4(a[mt][0], a[mt][1], a[mt][2], a[mt][3],
                            Apan + a_base + mt * (16 * 80) + kh * 32);
#pragma unroll
                for (int nt = 0; nt < 2; nt++)
                    LDSM_X4T(b[nt][0], b[nt][1], b[nt][2], b[nt][3],
                             Bk + b_off[nt] + kh * 4096);
#pragma unroll
                for (int mt = 0; mt < 4; mt++) {
                    MMA16816(acc[mt][0], a[mt], b[0][0], b[0][1]);
                    MMA16816(acc[mt][1], a[mt], b[0][2], b[0][3]);
                    MMA16816(acc[mt][2], a[mt], b[1][0], b[1][1]);
                    MMA16816(acc[mt][3], a[mt], b[1][2], b[1][3]);
                }
            }
        }

        // epilogue: write Cc (bf16 split) into H panels at (j=row, m=col)
        const int er = lane >> 2, ec = (lane & 3) * 2;
#pragma unroll
        for (int mt = 0; mt < 4; mt++) {
#pragma unroll
            for (int jj = 0; jj < 4; jj++) {
                int row = wm + mt * 16 + er;
                int col = wn128 + jj * 8 + ec;          // even
                uint32_t po = (uint32_t)(col >> 5) * FK_PANEL + (uint32_t)(col & 31) * 2;
                bf16 h0, l0, h1, l1;
                split1(acc[mt][jj][0], h0, l0); split1(acc[mt][jj][1], h1, l1);
                *(__nv_bfloat162*)(smem + FK_PH_OFF + po + row * 80) = __nv_bfloat162(h0, h1);
                *(__nv_bfloat162*)(smem + FK_PH_OFF + 4 * FK_PANEL + po + row * 80) = __nv_bfloat162(l0, l1);
                split1(acc[mt][jj][2], h0, l0); split1(acc[mt][jj][3], h1, l1);
                *(__nv_bfloat162*)(smem + FK_PH_OFF + po + (row + 8) * 80) = __nv_bfloat162(h0, h1);
                *(__nv_bfloat162*)(smem + FK_PH_OFF + 4 * FK_PANEL + po + (row + 8) * 80) = __nv_bfloat162(l0, l1);
            }
        }
    }
    __syncthreads();

    // ---- phase 2: in-place chunk scan (thread s owns complex mode s) -----
    if (tid < 64) {
        const int s = tid;
        const float a = Ar[n * 64 + s], w = Ai[n * 64 + s];
        const float p64 = expf(64.f * a);
        const float c64 = p64 * cosf(64.f * w), s64 = p64 * sinf(64.f * w);
        float hr = 0.f, hi = 0.f;
        const int col = 2 * s;
        char* hbase = smem + FK_PH_OFF + (uint32_t)(col >> 5) * FK_PANEL + (uint32_t)(col & 31) * 2;
        char* lbase = hbase + 4 * FK_PANEL;
#pragma unroll 4
        for (int j = 0; j < NCHK; j++) {
            __nv_bfloat162 chv = *(__nv_bfloat162*)(hbase + j * 80);
            __nv_bfloat162 clv = *(__nv_bfloat162*)(lbase + j * 80);
            float cr = __bfloat162float(chv.x) + __bfloat162float(clv.x);
            float ci = __bfloat162float(chv.y) + __bfloat162float(clv.y);
            bf16 h0, l0, h1, l1;
            split1(hr, h0, l0); split1(hi, h1, l1);
            *(__nv_bfloat162*)(hbase + j * 80) = __nv_bfloat162(h0, h1);
            *(__nv_bfloat162*)(lbase + j * 80) = __nv_bfloat162(l0, l1);
            float nr = c64 * hr - s64 * hi + cr;
            float ni = c64 * hi + s64 * hr + ci;
            hr = nr; hi = ni;
        }
    }
    __syncthreads();

    // ---- phase 3: conv MMAs ---------------------------------------------
    {
        const int wn = (wid & 3) * 16;
        float acc[4][2][4];
#pragma unroll
        for (int mt = 0; mt < 4; mt++)
#pragma unroll
            for (int j = 0; j < 2; j++)
#pragma unroll
                for (int r = 0; r < 4; r++) acc[mt][j][r] = 0.f;

#pragma unroll
        for (int cl = 0; cl < 18; cl++) {
            const int term = cl / 6, kc = cl % 6;
            // A panel
            uint32_t Apan;
            if (kc < 2)
                Apan = sb + FK_PX_OFF + (uint32_t)(((term < 2) ? 0 : 2) + kc) * FK_PANEL;
            else
                Apan = sb + FK_PH_OFF + (uint32_t)(((term < 2) ? 0 : 4) + (kc - 2)) * FK_PANEL;
            const uint32_t Bbase = sb + FK_WB_OFF + ((term == 1) ? 24576u : 0u)
                                 + (uint32_t)kc * 4096;
#pragma unroll
            for (int kh = 0; kh < 2; kh++) {
                uint32_t a[4][4], b[4];
#pragma unroll
                for (int mt = 0; mt < 4; mt++)
                    LDSM_X4(a[mt][0], a[mt][1], a[mt][2], a[mt][3],
                            Apan + a_base + mt * (16 * 80) + kh * 32);
                {
                    int krow = kh * 16 + (lane & 15);
                    int g = (wn >> 3) + (lane >> 4);
                    uint32_t boff = (uint32_t)krow * 128 + (uint32_t)(((g ^ (krow & 7)) & 7) * 16);
                    LDSM_X4T(b[0], b[1], b[2], b[3], Bbase + boff);
                }
#pragma unroll
                for (int mt = 0; mt < 4; mt++) {
                    MMA16816(acc[mt][0], a[mt], b[0], b[1]);
                    MMA16816(acc[mt][1], a[mt], b[2], b[3]);
                }
            }
        }

        const int er = lane >> 2, ec = (lane & 3) * 2;
        bf16* yhp = Yh + chain * L_DIM;
        bf16* ylp = Yl + chain * L_DIM;
#pragma unroll
        for (int mt = 0; mt < 4; mt++) {
#pragma unroll
            for (int j = 0; j < 2; j++) {
                int row0 = wm + mt * 16 + er;
                int tcol = wn + j * 8 + ec;
                size_t b0 = (size_t)row0 * 64 + tcol;
                bf16 h0, l0, h1, l1;
                split1(acc[mt][j][0], h0, l0); split1(acc[mt][j][1], h1, l1);
                *(__nv_bfloat162*)&yhp[b0] = __nv_bfloat162(h0, h1);
                *(__nv_bfloat162*)&ylp[b0] = __nv_bfloat162(l0, l1);
                size_t b1 = (size_t)(row0 + 8) * 64 + tcol;
                split1(acc[mt][j][2], h0, l0); split1(acc[mt][j][3], h1, l1);
                *(__nv_bfloat162*)&yhp[b1] = __nv_bfloat162(h0, h1);
                *(__nv_bfloat162*)&ylp[b1] = __nv_bfloat162(l0, l1);
            }
        }
    }
}

// ---------------------------------------------------------------------------
extern "C" void kernel_launch(void* const* d_in, const int* in_sizes, int n_in,
                              void* d_out, int out_size)
{
    const float* inp = (const float*)d_in[0];  // [B, C, L]
    const float* ar  = (const float*)d_in[1];  // [N, S]
    const float* ai  = (const float*)d_in[2];  // [N, S]
    const float* Bm  = (const float*)d_in[3];  // [N, C]
    const float* Cm  = (const float*)d_in[4];  // [C, N]
    const float* E   = (const float*)d_in[5];  // [N, S]
    float* out = (float*)d_out;                // [B, C, L]

    bf16 *inh, *inl, *xh, *xl, *yh, *yl, *bh, *bl, *ch, *cl;
    bf16 *wbh, *wbl, *wch, *wcl;
    cudaGetSymbolAddress((void**)&inh, g_inh);
    cudaGetSymbolAddress((void**)&inl, g_inl);
    cudaGetSymbolAddress((void**)&xh,  g_xh);
    cudaGetSymbolAddress((void**)&xl,  g_xl);
    cudaGetSymbolAddress((void**)&yh,  g_yh);
    cudaGetSymbolAddress((void**)&yl,  g_yl);
    cudaGetSymbolAddress((void**)&bh,  g_bh);
    cudaGetSymbolAddress((void**)&bl,  g_bl);
    cudaGetSymbolAddress((void**)&ch,  g_ch);
    cudaGetSymbolAddress((void**)&cl,  g_cl);
    cudaGetSymbolAddress((void**)&wbh, g_wbh);
    cudaGetSymbolAddress((void**)&wbl, g_wbl);
    cudaGetSymbolAddress((void**)&wch, g_wch);
    cudaGetSymbolAddress((void**)&wcl, g_wcl);

    cudaFuncSetAttribute(hgemm,        cudaFuncAttributeMaxDynamicSharedMemorySize, GEMM_SMEM);
    cudaFuncSetAttribute(prep_weights, cudaFuncAttributeMaxDynamicSharedMemorySize, PW_SMEM);
    cudaFuncSetAttribute(fused_mid,    cudaFuncAttributeMaxDynamicSharedMemorySize, FK_SMEM);

    const int n_in_elems = B_SZ * C_DIM * L_DIM;
    const int n_w = C_DIM * N_DIM;

    split_fp32<<<n_in_elems / 1024, 256>>>(inp, inh, inl, n_in_elems);
    split_fp32<<<n_w / 1024, 256>>>(Bm, bh, bl, n_w);
    split_fp32<<<n_w / 1024, 256>>>(Cm, ch, cl, n_w);
    prep_weights<<<N_DIM, 256, PW_SMEM>>>(ar, ai, E, wbh, wbl, wch, wcl);

    dim3 gg(L_DIM / 128, N_DIM / 128, B_SZ);
    hgemm<<<gg, 256, GEMM_SMEM>>>(bh, bl, inh, inl, nullptr, xh, xl);     // x = B@input

    fused_mid<<<dim3(B_SZ, N_DIM), 256, FK_SMEM>>>(xh, xl, wch, wcl, wbh, wbl, ar, ai, yh, yl);

    hgemm<<<gg, 256, GEMM_SMEM>>>(ch, cl, yh, yl, out, nullptr, nullptr); // out = C@y
}

// round 9
// speedup vs baseline: 1.6875x; 1.0261x over previous
#include <cuda_runtime.h>
#include <cuda_bf16.h>
#include <cstdint>
#include <math.h>

#define B_SZ   4
#define C_DIM  512
#define N_DIM  512
#define S_DIM  64
#define L_DIM  8192
#define NCHK   128

typedef __nv_bfloat16 bf16;

// ---------------------------------------------------------------------------
// Scratch (allocation-free rule: __device__ globals)
// ---------------------------------------------------------------------------
__device__ __align__(128) bf16  g_inh[(size_t)B_SZ * C_DIM * L_DIM];
__device__ __align__(128) bf16  g_inl[(size_t)B_SZ * C_DIM * L_DIM];
__device__ __align__(128) bf16  g_xh [(size_t)B_SZ * N_DIM * L_DIM];
__device__ __align__(128) bf16  g_xl [(size_t)B_SZ * N_DIM * L_DIM];
__device__ __align__(128) bf16  g_yh [(size_t)B_SZ * N_DIM * L_DIM];
__device__ __align__(128) bf16  g_yl [(size_t)B_SZ * N_DIM * L_DIM];
__device__ __align__(128) bf16  g_bh [C_DIM * N_DIM];
__device__ __align__(128) bf16  g_bl [C_DIM * N_DIM];
__device__ __align__(128) bf16  g_ch [C_DIM * N_DIM];
__device__ __align__(128) bf16  g_cl [C_DIM * N_DIM];
__device__ __align__(128) bf16  g_wbh[(size_t)N_DIM * 192 * 64];
__device__ __align__(128) bf16  g_wbl[(size_t)N_DIM * 192 * 64];
__device__ __align__(128) bf16  g_wch[(size_t)N_DIM * 64 * 128];
__device__ __align__(128) bf16  g_wcl[(size_t)N_DIM * 64 * 128];

// ---------------------------------------------------------------------------
// Helpers (base PTX only)
// ---------------------------------------------------------------------------
__device__ __forceinline__ uint32_t smem_u32(const void* p) {
    uint32_t a;
    asm("{ .reg .u64 t; cvta.to.shared.u64 t, %1; cvt.u32.u64 %0, t; }" : "=r"(a) : "l"(p));
    return a;
}
__device__ __forceinline__ void cpa16(uint32_t d, const void* s) {
    asm volatile("cp.async.cg.shared.global [%0], [%1], 16;" :: "r"(d), "l"(s));
}
#define CP_COMMIT()   asm volatile("cp.async.commit_group;" ::: "memory")
#define CP_WAIT2()    asm volatile("cp.async.wait_group 2;"  ::: "memory")
#define CP_WAIT1()    asm volatile("cp.async.wait_group 1;"  ::: "memory")
#define CP_WAIT_ALL() asm volatile("cp.async.wait_group 0;" ::: "memory")

#define LDSM_X4(r0,r1,r2,r3,addr) \
    asm volatile("ldmatrix.sync.aligned.m8n8.x4.shared.b16 {%0,%1,%2,%3}, [%4];" \
        : "=r"(r0), "=r"(r1), "=r"(r2), "=r"(r3) : "r"(addr))
#define LDSM_X4T(r0,r1,r2,r3,addr) \
    asm volatile("ldmatrix.sync.aligned.m8n8.x4.trans.shared.b16 {%0,%1,%2,%3}, [%4];" \
        : "=r"(r0), "=r"(r1), "=r"(r2), "=r"(r3) : "r"(addr))

#define MMA16816(d, a, b0v, b1v) \
    asm volatile("mma.sync.aligned.m16n8k16.row.col.f32.bf16.bf16.f32 " \
        "{%0,%1,%2,%3}, {%4,%5,%6,%7}, {%8,%9}, {%0,%1,%2,%3};" \
        : "+f"((d)[0]), "+f"((d)[1]), "+f"((d)[2]), "+f"((d)[3]) \
        : "r"((a)[0]), "r"((a)[1]), "r"((a)[2]), "r"((a)[3]), "r"(b0v), "r"(b1v))

__device__ __forceinline__ void split1(float v, bf16& h, bf16& l) {
    h = __float2bfloat16_rn(v);
    l = __float2bfloat16_rn(v - __bfloat162float(h));
}

// ---------------------------------------------------------------------------
// fp32 -> bf16 hi/lo split (pre-pass)
// ---------------------------------------------------------------------------
__global__ __launch_bounds__(256) void split_fp32(
    const float* __restrict__ src, bf16* __restrict__ hi, bf16* __restrict__ lo, int n)
{
    int i = (blockIdx.x * 256 + threadIdx.x) * 4;
    if (i >= n) return;
    float4 v = *(const float4*)(src + i);
    bf16 h0, l0, h1, l1, h2, l2, h3, l3;
    split1(v.x, h0, l0); split1(v.y, h1, l1);
    split1(v.z, h2, l2); split1(v.w, h3, l3);
    ((__nv_bfloat162*)(hi + i))[0] = __nv_bfloat162(h0, h1);
    ((__nv_bfloat162*)(hi + i))[1] = __nv_bfloat162(h2, h3);
    ((__nv_bfloat162*)(lo + i))[0] = __nv_bfloat162(l0, l1);
    ((__nv_bfloat162*)(lo + i))[1] = __nv_bfloat162(l2, l3);
}

// ---------------------------------------------------------------------------
// HMMA GEMM (proven 142us): Out[b] = W(512x512) @ X[b](512x8192)
// ---------------------------------------------------------------------------
#define STAGE   18432
#define A_BYTES 10240
#define NCHUNK  48
#define GEMM_SMEM (4 * STAGE)

__global__ __launch_bounds__(256, 2) void hgemm(
    const bf16* __restrict__ Ah, const bf16* __restrict__ Al,
    const bf16* __restrict__ Bh0, const bf16* __restrict__ Bl0,
    float* __restrict__ OutF, bf16* __restrict__ OutH, bf16* __restrict__ OutL)
{
    extern __shared__ char smem[];
    const uint32_t sb = smem_u32(smem);
    const int tid  = threadIdx.x;
    const int lane = tid & 31, wid = tid >> 5;
    const int n0 = blockIdx.x * 128;
    const int m0 = blockIdx.y * 128;
    const size_t boff = (size_t)blockIdx.z * C_DIM * L_DIM;
    const bf16* Bh = Bh0 + boff;
    const bf16* Bl = Bl0 + boff;

    const int am = tid >> 2, ac = tid & 3;
    const int bk = tid >> 4, bc = tid & 15;

    auto load_stage = [&](int cl, int st) {
        if (cl < NCHUNK) {
            const bf16* As = (cl < 32) ? Ah : Al;
            const bf16* Bs = (cl >= 16 && cl < 32) ? Bl : Bh;
            const int k0 = (cl & 15) << 5;
            const uint32_t s0 = sb + (uint32_t)st * STAGE;
            cpa16(s0 + am * 80 + ac * 16,
                  As + (size_t)(m0 + am) * C_DIM + k0 + ac * 8);
            cpa16(s0 + (am + 64) * 80 + ac * 16,
                  As + (size_t)(m0 + am + 64) * C_DIM + k0 + ac * 8);
            {
                int c1 = (bc & 8) | ((bc ^ (bk & 7)) & 7);
                cpa16(s0 + A_BYTES + bk * 256 + c1 * 16,
                      Bs + (size_t)(k0 + bk) * L_DIM + n0 + bc * 8);
                int k2 = bk + 16;
                int c2 = (bc & 8) | ((bc ^ (k2 & 7)) & 7);
                cpa16(s0 + A_BYTES + k2 * 256 + c2 * 16,
                      Bs + (size_t)(k0 + k2) * L_DIM + n0 + bc * 8);
            }
        }
        CP_COMMIT();
    };

    const int wm = (wid >> 2) * 64;
    const int wn = (wid & 3) * 32;
    const uint32_t a_base = (uint32_t)(wm + (lane & 15)) * 80 + ((lane >> 4) * 16);
    uint32_t b_off[2];
#pragma unroll
    for (int nt = 0; nt < 2; nt++) {
        int g  = (wn >> 3) + nt * 2 + (lane >> 4);
        int gp = (g & 8) | ((g ^ (lane & 7)) & 7);
        b_off[nt] = (uint32_t)(lane & 15) * 256 + gp * 16;
    }

    float acc[4][4][4];
#pragma unroll
    for (int mt = 0; mt < 4; mt++)
#pragma unroll
        for (int j = 0; j < 4; j++)
#pragma unroll
            for (int r = 0; r < 4; r++) acc[mt][j][r] = 0.f;

    load_stage(0, 0); load_stage(1, 1); load_stage(2, 2);

    for (int c = 0; c < NCHUNK; c++) {
        CP_WAIT2();
        __syncthreads();
        load_stage(c + 3, (c + 3) & 3);

        const uint32_t Abase = sb + (uint32_t)(c & 3) * STAGE;
        const uint32_t Bbase = Abase + A_BYTES;
#pragma unroll
        for (int kh = 0; kh < 2; kh++) {
            uint32_t a[4][4], b[2][4];
#pragma unroll
            for (int mt = 0; mt < 4; mt++)
                LDSM_X4(a[mt][0], a[mt][1], a[mt][2], a[mt][3],
                        Abase + a_base + mt * (16 * 80) + kh * 32);
#pragma unroll
            for (int nt = 0; nt < 2; nt++)
                LDSM_X4T(b[nt][0], b[nt][1], b[nt][2], b[nt][3],
                         Bbase + b_off[nt] + kh * 4096);
#pragma unroll
            for (int mt = 0; mt < 4; mt++) {
                MMA16816(acc[mt][0], a[mt], b[0][0], b[0][1]);
                MMA16816(acc[mt][1], a[mt], b[0][2], b[0][3]);
                MMA16816(acc[mt][2], a[mt], b[1][0], b[1][1]);
                MMA16816(acc[mt][3], a[mt], b[1][2], b[1][3]);
            }
        }
    }

    const int er = lane >> 2, ec = (lane & 3) * 2;
    const size_t outz = (size_t)blockIdx.z * N_DIM * L_DIM;
#pragma unroll
    for (int mt = 0; mt < 4; mt++) {
#pragma unroll
        for (int j = 0; j < 4; j++) {
            size_t base = outz + (size_t)(m0 + wm + mt * 16 + er) * L_DIM + (n0 + wn + j * 8 + ec);
            if (OutF) {
                *(float2*)&OutF[base]             = make_float2(acc[mt][j][0], acc[mt][j][1]);
                *(float2*)&OutF[base + 8 * L_DIM] = make_float2(acc[mt][j][2], acc[mt][j][3]);
            } else {
                bf16 h0, l0, h1, l1;
                split1(acc[mt][j][0], h0, l0); split1(acc[mt][j][1], h1, l1);
                *(__nv_bfloat162*)&OutH[base] = __nv_bfloat162(h0, h1);
                *(__nv_bfloat162*)&OutL[base] = __nv_bfloat162(l0, l1);
                split1(acc[mt][j][2], h0, l0); split1(acc[mt][j][3], h1, l1);
                *(__nv_bfloat162*)&OutH[base + 8 * L_DIM] = __nv_bfloat162(h0, h1);
                *(__nv_bfloat162*)&OutL[base + 8 * L_DIM] = __nv_bfloat162(l0, l1);
            }
        }
    }
}

// ---------------------------------------------------------------------------
// Prep (parallel, closed-form) — proven 20us
// ---------------------------------------------------------------------------
#define PW_WB_OFF 0
#define PW_WC_OFF (192 * 65)
#define PW_P_OFF  (PW_WC_OFF + 64 * 128)
#define PW_K_OFF  (PW_P_OFF + 64 * 65)
#define PW_SMEM   ((PW_K_OFF + 64) * 4)

__global__ __launch_bounds__(256) void prep_weights(
    const float* __restrict__ Ar, const float* __restrict__ Ai,
    const float* __restrict__ Ew,
    bf16* __restrict__ wbh, bf16* __restrict__ wbl,
    bf16* __restrict__ wch, bf16* __restrict__ wcl)
{
    extern __shared__ float sm[];
    float* sWb = sm + PW_WB_OFF;
    float* sWc = sm + PW_WC_OFF;
    float* sP  = sm + PW_P_OFF;
    float* sK  = sm + PW_K_OFF;

    const int n = blockIdx.x;
    const int tid = threadIdx.x;
    const int s = tid & 63;
    const int dg = tid >> 6;

    const float a = Ar[n * 64 + s], w = Ai[n * 64 + s], E = Ew[n * 64 + s];
    const float er = expf(a);
    const float lr = er * cosf(w), li = er * sinf(w);

#pragma unroll
    for (int dd = 0; dd < 16; dd++) {
        const int d = dg * 16 + dd;
        const float fd = (float)d;
        const float p  = expf(fd * a);
        const float cr = p * cosf(fd * w);
        const float ci = p * sinf(fd * w);
        sWc[(63 - d) * 128 + 2 * s]     = cr;
        sWc[(63 - d) * 128 + 2 * s + 1] = ci;
        sP[d * 65 + s] = E * cr;
        const float cr1 = cr * lr - ci * li;
        const float ci1 = cr * li + ci * lr;
        sWb[(64 + 2 * s) * 65 + d] = E * cr1;
        sWb[(65 + 2 * s) * 65 + d] = -E * ci1;
    }
    __syncthreads();
    if (tid < 64) {
        float acc = 0.f;
#pragma unroll
        for (int q = 0; q < 64; q++) acc += sP[tid * 65 + q];
        sK[tid] = acc;
    }
    __syncthreads();
    for (int i = tid; i < 64 * 64; i += 256) {
        int k = i >> 6, t = i & 63;
        sWb[k * 65 + t] = (t >= k) ? sK[t - k] : 0.f;
    }
    __syncthreads();
    {
        bf16* dh = wbh + (size_t)n * 192 * 64;
        bf16* dl = wbl + (size_t)n * 192 * 64;
        for (int i = tid; i < 192 * 64; i += 256) {
            int r = i >> 6, t = i & 63;
            bf16 h, l; split1(sWb[r * 65 + t], h, l);
            dh[i] = h; dl[i] = l;
        }
    }
    {
        bf16* dh = wch + (size_t)n * 64 * 128;
        bf16* dl = wcl + (size_t)n * 64 * 128;
        for (int i = tid; i < 64 * 128; i += 256) {
            bf16 h, l; split1(sWc[i], h, l);
            dh[i] = h; dl[i] = l;
        }
    }
}

// ---------------------------------------------------------------------------
// FUSED middle kernel with parallel segmented scan + load overlap.
// ---------------------------------------------------------------------------
#define FK_PANEL   10320
#define FK_PX_OFF  0
#define FK_PH_OFF  (4 * FK_PANEL)
#define FK_WC_OFF  (12 * FK_PANEL)
#define FK_WB_OFF  (FK_WC_OFF + 32768)
#define FK_END_OFF (FK_WB_OFF + 49152)      // segment end states: 4*64*2 floats
#define FK_SMEM    (FK_END_OFF + 2048)

__global__ __launch_bounds__(256, 1) void fused_mid(
    const bf16* __restrict__ Xh, const bf16* __restrict__ Xl,
    const bf16* __restrict__ Wch, const bf16* __restrict__ Wcl,
    const bf16* __restrict__ Wbh, const bf16* __restrict__ Wbl,
    const float* __restrict__ Ar, const float* __restrict__ Ai,
    bf16* __restrict__ Yh, bf16* __restrict__ Yl)
{
    extern __shared__ char smem[];
    const uint32_t sb = smem_u32(smem);
    const int tid  = threadIdx.x;
    const int lane = tid & 31, wid = tid >> 5;
    const int bb = blockIdx.x;
    const int n  = blockIdx.y;
    const size_t chain = (size_t)bb * N_DIM + n;

    // ---- group 0: x + Wc (needed for phase 1) ---------------------------
    for (int t = 0; t < 2; t++) {
        const bf16* src = (t == 0) ? (Xh + chain * L_DIM) : (Xl + chain * L_DIM);
        for (int q = tid; q < 1024; q += 256) {
            int j = q >> 3, c = q & 7;
            uint32_t dst = sb + FK_PX_OFF + (uint32_t)(t * 2 + (c >> 2)) * FK_PANEL
                         + j * 80 + (c & 3) * 16;
            cpa16(dst, src + (size_t)j * 64 + c * 8);
        }
    }
    for (int t = 0; t < 2; t++) {
        const bf16* src = ((t == 0) ? Wch : Wcl) + (size_t)n * 64 * 128;
        for (int q = tid; q < 1024; q += 256) {
            int r = q >> 4, c = q & 15;
            int cp = (c & 8) | ((c ^ (r & 7)) & 7);
            cpa16(sb + FK_WC_OFF + t * 16384 + r * 256 + cp * 16,
                  src + (size_t)r * 128 + c * 8);
        }
    }
    CP_COMMIT();
    // ---- group 1: Wb (needed only for phase 3; hidden behind p1+scan) ---
    for (int t = 0; t < 2; t++) {
        const bf16* src = ((t == 0) ? Wbh : Wbl) + (size_t)n * 192 * 64;
        for (int q = tid; q < 1536; q += 256) {
            int r = q >> 3, c = q & 7;
            int cp = c ^ (r & 7);
            cpa16(sb + FK_WB_OFF + t * 24576 + r * 128 + cp * 16,
                  src + (size_t)r * 64 + c * 8);
        }
    }
    CP_COMMIT();
    CP_WAIT1();
    __syncthreads();

    // ---- phase 1: contrib MMAs ------------------------------------------
    const int wm = (wid >> 2) * 64;
    const int wn128 = (wid & 3) * 32;
    const uint32_t a_base = (uint32_t)(wm + (lane & 15)) * 80 + ((lane >> 4) * 16);
    uint32_t b_off[2];
#pragma unroll
    for (int nt = 0; nt < 2; nt++) {
        int g  = (wn128 >> 3) + nt * 2 + (lane >> 4);
        int gp = (g & 8) | ((g ^ (lane & 7)) & 7);
        b_off[nt] = (uint32_t)(lane & 15) * 256 + gp * 16;
    }

    {
        float acc[4][4][4];
#pragma unroll
        for (int mt = 0; mt < 4; mt++)
#pragma unroll
            for (int j = 0; j < 4; j++)
#pragma unroll
                for (int r = 0; r < 4; r++) acc[mt][j][r] = 0.f;

#pragma unroll
        for (int cl = 0; cl < 6; cl++) {
            const uint32_t Apan = sb + FK_PX_OFF + (uint32_t)(((cl < 4) ? 0 : 2) + (cl & 1)) * FK_PANEL;
            const uint32_t Bk = sb + FK_WC_OFF + ((cl == 2 || cl == 3) ? 16384u : 0u)
                              + (uint32_t)((cl & 1) * 32) * 256;
#pragma unroll
            for (int kh = 0; kh < 2; kh++) {
                uint32_t a[4][4], b[2][4];
#pragma unroll
                for (int mt = 0; mt < 4; mt++)
                    LDSM_X4(a[mt][0], a[mt][1], a[mt][2], a[mt][3],
                            Apan + a_base + mt * (16 * 80) + kh * 32);
#pragma unroll
                for (int nt = 0; nt < 2; nt++)
                    LDSM_X4T(b[nt][0], b[nt][1], b[nt][2], b[nt][3],
                             Bk + b_off[nt] + kh * 4096);
#pragma unroll
                for (int mt = 0; mt < 4; mt++) {
                    MMA16816(acc[mt][0], a[mt], b[0][0], b[0][1]);
                    MMA16816(acc[mt][1], a[mt], b[0][2], b[0][3]);
                    MMA16816(acc[mt][2], a[mt], b[1][0], b[1][1]);
                    MMA16816(acc[mt][3], a[mt], b[1][2], b[1][3]);
                }
            }
        }

        const int er = lane >> 2, ec = (lane & 3) * 2;
#pragma unroll
        for (int mt = 0; mt < 4; mt++) {
#pragma unroll
            for (int jj = 0; jj < 4; jj++) {
                int row = wm + mt * 16 + er;
                int col = wn128 + jj * 8 + ec;
                uint32_t po = (uint32_t)(col >> 5) * FK_PANEL + (uint32_t)(col & 31) * 2;
                bf16 h0, l0, h1, l1;
                split1(acc[mt][jj][0], h0, l0); split1(acc[mt][jj][1], h1, l1);
                *(__nv_bfloat162*)(smem + FK_PH_OFF + po + row * 80) = __nv_bfloat162(h0, h1);
                *(__nv_bfloat162*)(smem + FK_PH_OFF + 4 * FK_PANEL + po + row * 80) = __nv_bfloat162(l0, l1);
                split1(acc[mt][jj][2], h0, l0); split1(acc[mt][jj][3], h1, l1);
                *(__nv_bfloat162*)(smem + FK_PH_OFF + po + (row + 8) * 80) = __nv_bfloat162(h0, h1);
                *(__nv_bfloat162*)(smem + FK_PH_OFF + 4 * FK_PANEL + po + (row + 8) * 80) = __nv_bfloat162(l0, l1);
            }
        }
    }
    __syncthreads();

    // ---- phase 2: 4-segment parallel scan (all 256 threads) --------------
    {
        const int s = tid & 63;
        const int g = tid >> 6;                // segment 0..3, 32 chunks each
        const float a = Ar[n * 64 + s], w = Ai[n * 64 + s];
        const float p64 = expf(64.f * a);
        const float c64 = p64 * cosf(64.f * w), s64 = p64 * sinf(64.f * w);
        const int col = 2 * s;
        char* hbase = smem + FK_PH_OFF + (uint32_t)(col >> 5) * FK_PANEL + (uint32_t)(col & 31) * 2;
        char* lbase = hbase + 4 * FK_PANEL;
        float* se = (float*)(smem + FK_END_OFF);
        const int j0 = g * 32;

        // step 1: local zero-seeded scan; slot j <- local state before chunk j
        float hr = 0.f, hi = 0.f;
#pragma unroll 8
        for (int jj = 0; jj < 32; jj++) {
            const int j = j0 + jj;
            __nv_bfloat162 chv = *(__nv_bfloat162*)(hbase + j * 80);
            __nv_bfloat162 clv = *(__nv_bfloat162*)(lbase + j * 80);
            float cr = __bfloat162float(chv.x) + __bfloat162float(clv.x);
            float ci = __bfloat162float(chv.y) + __bfloat162float(clv.y);
            bf16 h0, l0, h1, l1;
            split1(hr, h0, l0); split1(hi, h1, l1);
            *(__nv_bfloat162*)(hbase + j * 80) = __nv_bfloat162(h0, h1);
            *(__nv_bfloat162*)(lbase + j * 80) = __nv_bfloat162(l0, l1);
            float nr = c64 * hr - s64 * hi + cr;
            float ni = c64 * hi + s64 * hr + ci;
            hr = nr; hi = ni;
        }
        se[(g * 64 + s) * 2]     = hr;
        se[(g * 64 + s) * 2 + 1] = hi;
        __syncthreads();

        // step 2+3: prefix P_g = sum_{q<g} Lam^{2048(g-1-q)} end_q, then fix-up
        if (g > 0) {
            float pr = 0.f, pi = 0.f;
            for (int q = 0; q < g; q++) {
                float e = (float)(g - 1 - q);
                float pw = expf(2048.f * e * a);
                float cc = pw * cosf(2048.f * e * w), ss = pw * sinf(2048.f * e * w);
                float er_ = se[(q * 64 + s) * 2], ei_ = se[(q * 64 + s) * 2 + 1];
                pr += cc * er_ - ss * ei_;
                pi += cc * ei_ + ss * er_;
            }
            // V = Lam^{64*jj} * P_g ; slot j += V
            float vr = pr, vi = pi;
#pragma unroll 8
            for (int jj = 0; jj < 32; jj++) {
                const int j = j0 + jj;
                __nv_bfloat162 chv = *(__nv_bfloat162*)(hbase + j * 80);
                __nv_bfloat162 clv = *(__nv_bfloat162*)(lbase + j * 80);
                float sr = __bfloat162float(chv.x) + __bfloat162float(clv.x) + vr;
                float si = __bfloat162float(chv.y) + __bfloat162float(clv.y) + vi;
                bf16 h0, l0, h1, l1;
                split1(sr, h0, l0); split1(si, h1, l1);
                *(__nv_bfloat162*)(hbase + j * 80) = __nv_bfloat162(h0, h1);
                *(__nv_bfloat162*)(lbase + j * 80) = __nv_bfloat162(l0, l1);
                float nvr = c64 * vr - s64 * vi;
                float nvi = c64 * vi + s64 * vr;
                vr = nvr; vi = nvi;
            }
        }
    }
    CP_WAIT_ALL();
    __syncthreads();

    // ---- phase 3: conv MMAs ---------------------------------------------
    {
        const int wn = (wid & 3) * 16;
        float acc[4][2][4];
#pragma unroll
        for (int mt = 0; mt < 4; mt++)
#pragma unroll
            for (int j = 0; j < 2; j++)
#pragma unroll
                for (int r = 0; r < 4; r++) acc[mt][j][r] = 0.f;

#pragma unroll
        for (int cl = 0; cl < 18; cl++) {
            const int term = cl / 6, kc = cl % 6;
            uint32_t Apan;
            if (kc < 2)
                Apan = sb + FK_PX_OFF + (uint32_t)(((term < 2) ? 0 : 2) + kc) * FK_PANEL;
            else
                Apan = sb + FK_PH_OFF + (uint32_t)(((term < 2) ? 0 : 4) + (kc - 2)) * FK_PANEL;
            const uint32_t Bbase = sb + FK_WB_OFF + ((term == 1) ? 24576u : 0u)
                                 + (uint32_t)kc * 4096;
#pragma unroll
            for (int kh = 0; kh < 2; kh++) {
                uint32_t a[4][4], b[4];
#pragma unroll
                for (int mt = 0; mt < 4; mt++)
                    LDSM_X4(a[mt][0], a[mt][1], a[mt][2], a[mt][3],
                            Apan + a_base + mt * (16 * 80) + kh * 32);
                {
                    int krow = kh * 16 + (lane & 15);
                    int g = (wn >> 3) + (lane >> 4);
                    uint32_t boff = (uint32_t)krow * 128 + (uint32_t)(((g ^ (krow & 7)) & 7) * 16);
                    LDSM_X4T(b[0], b[1], b[2], b[3], Bbase + boff);
                }
#pragma unroll
                for (int mt = 0; mt < 4; mt++) {
                    MMA16816(acc[mt][0], a[mt], b[0], b[1]);
                    MMA16816(acc[mt][1], a[mt], b[2], b[3]);
                }
            }
        }

        const int er = lane >> 2, ec = (lane & 3) * 2;
        bf16* yhp = Yh + chain * L_DIM;
        bf16* ylp = Yl + chain * L_DIM;
#pragma unroll
        for (int mt = 0; mt < 4; mt++) {
#pragma unroll
            for (int j = 0; j < 2; j++) {
                int row0 = wm + mt * 16 + er;
                int tcol = wn + j * 8 + ec;
                size_t b0 = (size_t)row0 * 64 + tcol;
                bf16 h0, l0, h1, l1;
                split1(acc[mt][j][0], h0, l0); split1(acc[mt][j][1], h1, l1);
                *(__nv_bfloat162*)&yhp[b0] = __nv_bfloat162(h0, h1);
                *(__nv_bfloat162*)&ylp[b0] = __nv_bfloat162(l0, l1);
                size_t b1 = (size_t)(row0 + 8) * 64 + tcol;
                split1(acc[mt][j][2], h0, l0); split1(acc[mt][j][3], h1, l1);
                *(__nv_bfloat162*)&yhp[b1] = __nv_bfloat162(h0, h1);
                *(__nv_bfloat162*)&ylp[b1] = __nv_bfloat162(l0, l1);
            }
        }
    }
}

// ---------------------------------------------------------------------------
extern "C" void kernel_launch(void* const* d_in, const int* in_sizes, int n_in,
                              void* d_out, int out_size)
{
    const float* inp = (const float*)d_in[0];  // [B, C, L]
    const float* ar  = (const float*)d_in[1];  // [N, S]
    const float* ai  = (const float*)d_in[2];  // [N, S]
    const float* Bm  = (const float*)d_in[3];  // [N, C]
    const float* Cm  = (const float*)d_in[4];  // [C, N]
    const float* E   = (const float*)d_in[5];  // [N, S]
    float* out = (float*)d_out;                // [B, C, L]

    bf16 *inh, *inl, *xh, *xl, *yh, *yl, *bh, *bl, *ch, *cl;
    bf16 *wbh, *wbl, *wch, *wcl;
    cudaGetSymbolAddress((void**)&inh, g_inh);
    cudaGetSymbolAddress((void**)&inl, g_inl);
    cudaGetSymbolAddress((void**)&xh,  g_xh);
    cudaGetSymbolAddress((void**)&xl,  g_xl);
    cudaGetSymbolAddress((void**)&yh,  g_yh);
    cudaGetSymbolAddress((void**)&yl,  g_yl);
    cudaGetSymbolAddress((void**)&bh,  g_bh);
    cudaGetSymbolAddress((void**)&bl,  g_bl);
    cudaGetSymbolAddress((void**)&ch,  g_ch);
    cudaGetSymbolAddress((void**)&cl,  g_cl);
    cudaGetSymbolAddress((void**)&wbh, g_wbh);
    cudaGetSymbolAddress((void**)&wbl, g_wbl);
    cudaGetSymbolAddress((void**)&wch, g_wch);
    cudaGetSymbolAddress((void**)&wcl, g_wcl);

    cudaFuncSetAttribute(hgemm,        cudaFuncAttributeMaxDynamicSharedMemorySize, GEMM_SMEM);
    cudaFuncSetAttribute(prep_weights, cudaFuncAttributeMaxDynamicSharedMemorySize, PW_SMEM);
    cudaFuncSetAttribute(fused_mid,    cudaFuncAttributeMaxDynamicSharedMemorySize, FK_SMEM);

    const int n_in_elems = B_SZ * C_DIM * L_DIM;
    const int n_w = C_DIM * N_DIM;

    split_fp32<<<n_in_elems / 1024, 256>>>(inp, inh, inl, n_in_elems);
    split_fp32<<<n_w / 1024, 256>>>(Bm, bh, bl, n_w);
    split_fp32<<<n_w / 1024, 256>>>(Cm, ch, cl, n_w);
    prep_weights<<<N_DIM, 256, PW_SMEM>>>(ar, ai, E, wbh, wbl, wch, wcl);

    dim3 gg(L_DIM / 128, N_DIM / 128, B_SZ);
    hgemm<<<gg, 256, GEMM_SMEM>>>(bh, bl, inh, inl, nullptr, xh, xl);     // x = B@input

    fused_mid<<<dim3(B_SZ, N_DIM), 256, FK_SMEM>>>(xh, xl, wch, wcl, wbh, wbl, ar, ai, yh, yl);

    hgemm<<<gg, 256, GEMM_SMEM>>>(ch, cl, yh, yl, out, nullptr, nullptr); // out = C@y
}